// round 1
// baseline (speedup 1.0000x reference)
#include <cuda_runtime.h>

// ---------------------------------------------------------------------------
// LongTermMemory: h = relu(x@W1+b1); m = h@W2+b2; q,k,v = m@{q,k,v}_w + b;
// out = sliding-window attention(q,k,v), window=65 (+-32), scale=1/32.
// B=2, S=2048, DIM=1024 -> M_TOT=4096 rows.
// ---------------------------------------------------------------------------

constexpr int M_TOT = 4096;
constexpr int DIMC  = 1024;
constexpr int SEQ   = 2048;
constexpr int HALF  = 32;
constexpr int WIN   = 65;

// Scratch (allocation-free rule: __device__ globals)
__device__ float g_h[M_TOT * DIMC];
__device__ float g_m[M_TOT * DIMC];
__device__ float g_q[M_TOT * DIMC];
__device__ float g_k[M_TOT * DIMC];
__device__ float g_v[M_TOT * DIMC];

// ---------------------------------------------------------------------------
// SGEMM: C[M,N] = A[M,K] @ B[K,N] + bias, optional ReLU.
// 128x128 block tile, BK=8, 256 threads, 8x8 per-thread micro-tile.
// ---------------------------------------------------------------------------
template <int RELU>
__global__ __launch_bounds__(256, 2)
void sgemm_bias_kernel(const float* __restrict__ A, const float* __restrict__ B,
                       const float* __restrict__ bias, float* __restrict__ C,
                       int M, int N, int K)
{
    constexpr int BM = 128, BN = 128, BK = 8;
    __shared__ float As[BK][BM];
    __shared__ float Bs[BK][BN];

    const int tid = threadIdx.x;
    const int bx = blockIdx.x;   // N tile
    const int by = blockIdx.y;   // M tile

    const float* Ab = A + (size_t)by * BM * K;
    const float* Bb = B + (size_t)bx * BN;
    float*       Cb = C + (size_t)by * BM * N + (size_t)bx * BN;

    // loaders
    const int arow = tid >> 1;          // 0..127
    const int acol = (tid & 1) << 2;    // 0 or 4
    const int brow = tid >> 5;          // 0..7
    const int bcol = (tid & 31) << 2;   // 0..124

    // compute mapping
    const int tr = (tid >> 4) << 3;     // 0..120
    const int tc = (tid & 15) << 3;     // 0..120

    float acc[8][8] = {};

    for (int kt = 0; kt < K; kt += BK) {
        float4 av = *(const float4*)(Ab + (size_t)arow * K + kt + acol);
        As[acol + 0][arow] = av.x;
        As[acol + 1][arow] = av.y;
        As[acol + 2][arow] = av.z;
        As[acol + 3][arow] = av.w;
        *(float4*)(&Bs[brow][bcol]) =
            *(const float4*)(Bb + (size_t)(kt + brow) * N + bcol);
        __syncthreads();

        #pragma unroll
        for (int k = 0; k < BK; k++) {
            float4 a0 = *(const float4*)&As[k][tr];
            float4 a1 = *(const float4*)&As[k][tr + 4];
            float4 b0 = *(const float4*)&Bs[k][tc];
            float4 b1 = *(const float4*)&Bs[k][tc + 4];
            float am[8] = {a0.x, a0.y, a0.z, a0.w, a1.x, a1.y, a1.z, a1.w};
            float bn[8] = {b0.x, b0.y, b0.z, b0.w, b1.x, b1.y, b1.z, b1.w};
            #pragma unroll
            for (int i = 0; i < 8; i++)
                #pragma unroll
                for (int j = 0; j < 8; j++)
                    acc[i][j] = fmaf(am[i], bn[j], acc[i][j]);
        }
        __syncthreads();
    }

    float bvals[8];
    #pragma unroll
    for (int j = 0; j < 8; j++) bvals[j] = bias[bx * BN + tc + j];

    #pragma unroll
    for (int i = 0; i < 8; i++) {
        float r[8];
        #pragma unroll
        for (int j = 0; j < 8; j++) {
            float vv = acc[i][j] + bvals[j];
            if (RELU) vv = fmaxf(vv, 0.0f);
            r[j] = vv;
        }
        *(float4*)(Cb + (size_t)(tr + i) * N + tc)     = make_float4(r[0], r[1], r[2], r[3]);
        *(float4*)(Cb + (size_t)(tr + i) * N + tc + 4) = make_float4(r[4], r[5], r[6], r[7]);
    }
}

// ---------------------------------------------------------------------------
// Sliding-window attention. One block per query row (4096 blocks, 256 thr).
// Phase 1: 8 warps compute the 65 dot products (k reads hit L2; k/v = 32MB).
// Phase 2: warp-0 softmax in smem.
// Phase 3: each thread owns one float4 of the output dim, accumulates over
//          the window from v.
// ---------------------------------------------------------------------------
__global__ __launch_bounds__(256)
void swa_kernel(const float* __restrict__ q, const float* __restrict__ k,
                const float* __restrict__ v, float* __restrict__ out)
{
    __shared__ float4 qs4[DIMC / 4];   // scaled q row
    __shared__ float  sc[WIN];

    const int row = blockIdx.x;          // 0..4095
    const int b   = row >> 11;
    const int s   = row & (SEQ - 1);
    const int tid = threadIdx.x;
    const int warp = tid >> 5;
    const int lane = tid & 31;

    const float scale = 0.03125f;        // 1/sqrt(1024)

    // load + scale q
    {
        float4 t = ((const float4*)(q + (size_t)row * DIMC))[tid];
        t.x *= scale; t.y *= scale; t.z *= scale; t.w *= scale;
        qs4[tid] = t;
    }
    __syncthreads();

    // scores
    for (int p = warp; p < WIN; p += 8) {
        const int j = s - HALF + p;
        if (j < 0 || j >= SEQ) {
            if (lane == 0) sc[p] = -__int_as_float(0x7f800000);  // -inf
            continue;
        }
        const float4* kr = (const float4*)(k + ((size_t)b * SEQ + j) * DIMC);
        float acc = 0.0f;
        for (int c = lane; c < DIMC / 4; c += 32) {
            float4 kv = kr[c];
            float4 qv = qs4[c];
            acc = fmaf(qv.x, kv.x, acc);
            acc = fmaf(qv.y, kv.y, acc);
            acc = fmaf(qv.z, kv.z, acc);
            acc = fmaf(qv.w, kv.w, acc);
        }
        #pragma unroll
        for (int off = 16; off; off >>= 1)
            acc += __shfl_xor_sync(0xffffffffu, acc, off);
        if (lane == 0) sc[p] = acc;
    }
    __syncthreads();

    // softmax (warp 0)
    if (tid < 32) {
        float mx = -__int_as_float(0x7f800000);
        for (int p = tid; p < WIN; p += 32) mx = fmaxf(mx, sc[p]);
        #pragma unroll
        for (int off = 16; off; off >>= 1)
            mx = fmaxf(mx, __shfl_xor_sync(0xffffffffu, mx, off));
        float sum = 0.0f;
        float e[3]; int np = 0;
        for (int p = tid; p < WIN; p += 32) {
            float ev = __expf(sc[p] - mx);
            e[np++] = ev;
            sum += ev;
        }
        #pragma unroll
        for (int off = 16; off; off >>= 1)
            sum += __shfl_xor_sync(0xffffffffu, sum, off);
        float inv = 1.0f / sum;
        np = 0;
        for (int p = tid; p < WIN; p += 32) sc[p] = e[np++] * inv;
    }
    __syncthreads();

    // output: thread tid owns float4 chunk tid of the 1024-dim row
    const int j0 = (s - HALF < 0) ? 0 : s - HALF;
    const int j1 = (s + HALF > SEQ - 1) ? SEQ - 1 : s + HALF;
    float4 acc = make_float4(0.f, 0.f, 0.f, 0.f);
    const float4* vb = (const float4*)(v + (size_t)b * SEQ * DIMC);
    for (int j = j0; j <= j1; j++) {
        const float w = sc[j - (s - HALF)];
        float4 vv = vb[(size_t)j * (DIMC / 4) + tid];
        acc.x = fmaf(w, vv.x, acc.x);
        acc.y = fmaf(w, vv.y, acc.y);
        acc.z = fmaf(w, vv.z, acc.z);
        acc.w = fmaf(w, vv.w, acc.w);
    }
    ((float4*)(out + (size_t)row * DIMC))[tid] = acc;
}

// ---------------------------------------------------------------------------
// launch
// ---------------------------------------------------------------------------
extern "C" void kernel_launch(void* const* d_in, const int* in_sizes, int n_in,
                              void* d_out, int out_size)
{
    const float* x     = (const float*)d_in[0];
    const float* nm_w1 = (const float*)d_in[1];
    const float* nm_b1 = (const float*)d_in[2];
    const float* nm_w2 = (const float*)d_in[3];
    const float* nm_b2 = (const float*)d_in[4];
    const float* q_w   = (const float*)d_in[5];
    const float* q_b   = (const float*)d_in[6];
    const float* k_w   = (const float*)d_in[7];
    const float* k_b   = (const float*)d_in[8];
    const float* v_w   = (const float*)d_in[9];
    const float* v_b   = (const float*)d_in[10];
    float* out = (float*)d_out;

    float *h, *m, *q, *k, *v;
    cudaGetSymbolAddress((void**)&h, g_h);
    cudaGetSymbolAddress((void**)&m, g_m);
    cudaGetSymbolAddress((void**)&q, g_q);
    cudaGetSymbolAddress((void**)&k, g_k);
    cudaGetSymbolAddress((void**)&v, g_v);

    dim3 grid(DIMC / 128, M_TOT / 128);   // (8, 32)
    dim3 block(256);

    sgemm_bias_kernel<1><<<grid, block>>>(x, nm_w1, nm_b1, h, M_TOT, DIMC, DIMC);
    sgemm_bias_kernel<0><<<grid, block>>>(h, nm_w2, nm_b2, m, M_TOT, DIMC, DIMC);
    sgemm_bias_kernel<0><<<grid, block>>>(m, q_w, q_b, q, M_TOT, DIMC, DIMC);
    sgemm_bias_kernel<0><<<grid, block>>>(m, k_w, k_b, k, M_TOT, DIMC, DIMC);
    sgemm_bias_kernel<0><<<grid, block>>>(m, v_w, v_b, v, M_TOT, DIMC, DIMC);

    swa_kernel<<<M_TOT, 256>>>(q, k, v, out);
}

// round 3
// speedup vs baseline: 1.9166x; 1.9166x over previous
#include <cuda_runtime.h>
#include <cuda_bf16.h>
#include <cstdint>

// ---------------------------------------------------------------------------
// LongTermMemory via mma.sync (HMMA) bf16 hi/lo split GEMMs.
// tcgen05 is unavailable: harness compiles PTX at compute_103 (no 'a'),
// which rejects tcgen05.*. mma.sync.m16n8k16.bf16 is baseline PTX.
// Numerics: fp32 operand a = hi + lo (both bf16); D += Ah*Bh + Ah*Bl + Al*Bh
// with fp32 accumulators -> ~2^-16 relative error, far under 1e-3 gate.
// ---------------------------------------------------------------------------

constexpr int M_TOT = 4096;
constexpr int DIMC  = 1024;
constexpr int SEQ   = 2048;
constexpr int HALF  = 32;
constexpr int WIN   = 65;

// ---------------- scratch ----------------
__device__ __nv_bfloat16 g_x_hi[M_TOT * DIMC];
__device__ __nv_bfloat16 g_x_lo[M_TOT * DIMC];
__device__ __nv_bfloat16 g_h_hi[M_TOT * DIMC];
__device__ __nv_bfloat16 g_h_lo[M_TOT * DIMC];
__device__ __nv_bfloat16 g_m_hi[M_TOT * DIMC];
__device__ __nv_bfloat16 g_m_lo[M_TOT * DIMC];
__device__ float g_q[M_TOT * DIMC];
__device__ float g_k[M_TOT * DIMC];
__device__ float g_v[M_TOT * DIMC];
__device__ __nv_bfloat16 g_w_hi[5][DIMC * DIMC];   // transposed: Wt[n][k]
__device__ __nv_bfloat16 g_w_lo[5][DIMC * DIMC];

// ---------------------------------------------------------------------------
// helpers
// ---------------------------------------------------------------------------
__device__ __forceinline__ uint32_t smem_u32(const void* p) {
    uint32_t a;
    asm("{ .reg .u64 t; cvta.to.shared.u64 t, %1; cvt.u32.u64 %0, t; }"
        : "=r"(a) : "l"(p));
    return a;
}
__device__ __forceinline__ void cp_async16(uint32_t saddr, const void* gaddr) {
    asm volatile("cp.async.cg.shared.global [%0], [%1], 16;"
                 :: "r"(saddr), "l"(gaddr));
}
#define CP_COMMIT()  asm volatile("cp.async.commit_group;" ::: "memory")
#define CP_WAIT(N)   asm volatile("cp.async.wait_group %0;" :: "n"(N) : "memory")

__device__ __forceinline__ void mma16816(float* d, const uint32_t* a, const uint32_t* b) {
    asm volatile(
        "mma.sync.aligned.m16n8k16.row.col.f32.bf16.bf16.f32 "
        "{%0,%1,%2,%3}, {%4,%5,%6,%7}, {%8,%9}, {%0,%1,%2,%3};"
        : "+f"(d[0]), "+f"(d[1]), "+f"(d[2]), "+f"(d[3])
        : "r"(a[0]), "r"(a[1]), "r"(a[2]), "r"(a[3]), "r"(b[0]), "r"(b[1]));
}

__device__ __forceinline__ void split_bf16(float v, __nv_bfloat16& hi, __nv_bfloat16& lo) {
    hi = __float2bfloat16(v);
    lo = __float2bfloat16(v - __bfloat162float(hi));
}

// ---------------------------------------------------------------------------
// conversion kernels
// ---------------------------------------------------------------------------
__global__ void split_x_kernel(const float* __restrict__ x,
                               __nv_bfloat16* __restrict__ hi,
                               __nv_bfloat16* __restrict__ lo, int n4) {
    int i = blockIdx.x * blockDim.x + threadIdx.x;
    if (i >= n4) return;
    float4 v = ((const float4*)x)[i];
    __nv_bfloat16 h0, h1, h2, h3, l0, l1, l2, l3;
    split_bf16(v.x, h0, l0); split_bf16(v.y, h1, l1);
    split_bf16(v.z, h2, l2); split_bf16(v.w, h3, l3);
    __nv_bfloat162* hp = (__nv_bfloat162*)hi;
    __nv_bfloat162* lp = (__nv_bfloat162*)lo;
    hp[2 * i]     = __nv_bfloat162(h0, h1);
    hp[2 * i + 1] = __nv_bfloat162(h2, h3);
    lp[2 * i]     = __nv_bfloat162(l0, l1);
    lp[2 * i + 1] = __nv_bfloat162(l2, l3);
}

__global__ void transpose_split_kernel(const float* __restrict__ W,
                                       __nv_bfloat16* __restrict__ hi,
                                       __nv_bfloat16* __restrict__ lo) {
    __shared__ float t[32][33];
    const int n0 = blockIdx.x * 32, k0 = blockIdx.y * 32;
    const int tx = threadIdx.x, ty = threadIdx.y;
    #pragma unroll
    for (int i = ty; i < 32; i += 8)
        t[i][tx] = W[(size_t)(k0 + i) * DIMC + n0 + tx];
    __syncthreads();
    #pragma unroll
    for (int i = ty; i < 32; i += 8) {
        float v = t[tx][i];
        __nv_bfloat16 h, l; split_bf16(v, h, l);
        size_t o = (size_t)(n0 + i) * DIMC + k0 + tx;
        hi[o] = h; lo[o] = l;
    }
}

// ---------------------------------------------------------------------------
// HMMA GEMM: C[4096,1024] = A @ Bt^T + bias (A [m][k], Bt [n][k], bf16 hi/lo)
// CTA tile 128x128, BK=32, 8 warps (2x4), warp tile 64x32, double-buffered
// cp.async. Smem row stride 40 bf16 (80B) -> conflict-free frag loads.
// ---------------------------------------------------------------------------
constexpr int BK = 32;
constexpr int LDS_STRIDE = 40;                       // elements
constexpr int TILE_E = 128 * LDS_STRIDE;             // 5120 elements
constexpr int TILE_B = TILE_E * 2;                   // 10240 bytes
constexpr int STAGE_B = 4 * TILE_B;                  // 40960 bytes
constexpr int GEMM_SMEM = 2 * STAGE_B;               // 81920 bytes

template <int RELU, int OUT_F32, int OUT_BF16>
__global__ __launch_bounds__(256, 1)
void gemm_hmma_kernel(const __nv_bfloat16* __restrict__ A_hi,
                      const __nv_bfloat16* __restrict__ A_lo,
                      const __nv_bfloat16* __restrict__ B_hi,
                      const __nv_bfloat16* __restrict__ B_lo,
                      const float* __restrict__ bias,
                      float* __restrict__ Cf,
                      __nv_bfloat16* __restrict__ C_hi,
                      __nv_bfloat16* __restrict__ C_lo)
{
    extern __shared__ __nv_bfloat16 sm[];
    const uint32_t sb = smem_u32(sm);

    const int tid  = threadIdx.x;
    const int wid  = tid >> 5;
    const int lane = tid & 31;
    const int bx = blockIdx.x;     // N tile
    const int by = blockIdx.y;     // M tile

    const int wr = wid >> 2;       // 0..1 -> m offset 64*wr
    const int wc = wid & 3;        // 0..3 -> n offset 32*wc
    const int g   = lane >> 2;     // 0..7
    const int tig = lane & 3;      // 0..3

    // global row bases for the 4 tiles (Ah, Al, Bh, Bl)
    const __nv_bfloat16* srcA_hi = A_hi + (size_t)by * 128 * DIMC;
    const __nv_bfloat16* srcA_lo = A_lo + (size_t)by * 128 * DIMC;
    const __nv_bfloat16* srcB_hi = B_hi + (size_t)bx * 128 * DIMC;
    const __nv_bfloat16* srcB_lo = B_lo + (size_t)bx * 128 * DIMC;

    const int lrow0 = tid >> 2;     // 0..63
    const int lkc   = tid & 3;      // 16B chunk within 64B row-chunk

    auto load_stage = [&](int stage, int kt) {
        const uint32_t s0 = sb + stage * STAGE_B;
        const size_t gofs = (size_t)0 * DIMC + kt * BK + lkc * 8;
        #pragma unroll
        for (int half = 0; half < 2; half++) {
            const int row = lrow0 + 64 * half;
            const size_t go = (size_t)row * DIMC + kt * BK + lkc * 8;
            const uint32_t so = row * (LDS_STRIDE * 2) + lkc * 16;
            cp_async16(s0 + 0 * TILE_B + so, srcA_hi + go);
            cp_async16(s0 + 1 * TILE_B + so, srcA_lo + go);
            cp_async16(s0 + 2 * TILE_B + so, srcB_hi + go);
            cp_async16(s0 + 3 * TILE_B + so, srcB_lo + go);
        }
        (void)gofs;
    };

    float acc[4][4][4];
    #pragma unroll
    for (int i = 0; i < 4; i++)
        #pragma unroll
        for (int j = 0; j < 4; j++)
            #pragma unroll
            for (int r = 0; r < 4; r++) acc[i][j][r] = 0.0f;

    load_stage(0, 0);
    CP_COMMIT();

    constexpr int NKT = DIMC / BK;   // 32
    for (int kt = 0; kt < NKT; kt++) {
        const int stage = kt & 1;
        if (kt + 1 < NKT) {
            load_stage((kt + 1) & 1, kt + 1);
            CP_COMMIT();
            CP_WAIT(1);
        } else {
            CP_WAIT(0);
        }
        __syncthreads();

        const __nv_bfloat16* stAh = sm + stage * (STAGE_B / 2);
        const __nv_bfloat16* stAl = stAh + TILE_E;
        const __nv_bfloat16* stBh = stAh + 2 * TILE_E;
        const __nv_bfloat16* stBl = stAh + 3 * TILE_E;

        #pragma unroll
        for (int s = 0; s < 2; s++) {
            const int k0 = s * 16;
            uint32_t ah[4][4], al[4][4], bh[4][2], bl[4][2];
            #pragma unroll
            for (int i = 0; i < 4; i++) {
                const int m0 = wr * 64 + i * 16;
                const int r0 = (m0 + g) * LDS_STRIDE + k0 + tig * 2;
                const int r1 = (m0 + g + 8) * LDS_STRIDE + k0 + tig * 2;
                ah[i][0] = *(const uint32_t*)(stAh + r0);
                ah[i][1] = *(const uint32_t*)(stAh + r1);
                ah[i][2] = *(const uint32_t*)(stAh + r0 + 8);
                ah[i][3] = *(const uint32_t*)(stAh + r1 + 8);
                al[i][0] = *(const uint32_t*)(stAl + r0);
                al[i][1] = *(const uint32_t*)(stAl + r1);
                al[i][2] = *(const uint32_t*)(stAl + r0 + 8);
                al[i][3] = *(const uint32_t*)(stAl + r1 + 8);
            }
            #pragma unroll
            for (int j = 0; j < 4; j++) {
                const int n0 = wc * 32 + j * 8;
                const int rb = (n0 + g) * LDS_STRIDE + k0 + tig * 2;
                bh[j][0] = *(const uint32_t*)(stBh + rb);
                bh[j][1] = *(const uint32_t*)(stBh + rb + 8);
                bl[j][0] = *(const uint32_t*)(stBl + rb);
                bl[j][1] = *(const uint32_t*)(stBl + rb + 8);
            }
            #pragma unroll
            for (int i = 0; i < 4; i++)
                #pragma unroll
                for (int j = 0; j < 4; j++) {
                    mma16816(acc[i][j], ah[i], bh[j]);
                    mma16816(acc[i][j], ah[i], bl[j]);
                    mma16816(acc[i][j], al[i], bh[j]);
                }
        }
        __syncthreads();
    }

    // ---- epilogue ----
    #pragma unroll
    for (int i = 0; i < 4; i++) {
        const int mg0 = by * 128 + wr * 64 + i * 16 + g;
        #pragma unroll
        for (int j = 0; j < 4; j++) {
            const int ng = bx * 128 + wc * 32 + j * 8 + tig * 2;
            const float b0 = __ldg(bias + ng);
            const float b1 = __ldg(bias + ng + 1);
            float v00 = acc[i][j][0] + b0;
            float v01 = acc[i][j][1] + b1;
            float v10 = acc[i][j][2] + b0;
            float v11 = acc[i][j][3] + b1;
            if (RELU) {
                v00 = fmaxf(v00, 0.0f); v01 = fmaxf(v01, 0.0f);
                v10 = fmaxf(v10, 0.0f); v11 = fmaxf(v11, 0.0f);
            }
            const size_t o0 = (size_t)mg0 * DIMC + ng;
            const size_t o1 = (size_t)(mg0 + 8) * DIMC + ng;
            if (OUT_F32) {
                *(float2*)(Cf + o0) = make_float2(v00, v01);
                *(float2*)(Cf + o1) = make_float2(v10, v11);
            }
            if (OUT_BF16) {
                __nv_bfloat16 h0, l0, h1, l1;
                split_bf16(v00, h0, l0); split_bf16(v01, h1, l1);
                *(__nv_bfloat162*)(C_hi + o0) = __nv_bfloat162(h0, h1);
                *(__nv_bfloat162*)(C_lo + o0) = __nv_bfloat162(l0, l1);
                split_bf16(v10, h0, l0); split_bf16(v11, h1, l1);
                *(__nv_bfloat162*)(C_hi + o1) = __nv_bfloat162(h0, h1);
                *(__nv_bfloat162*)(C_lo + o1) = __nv_bfloat162(l0, l1);
            }
        }
    }
}

// ---------------------------------------------------------------------------
// Sliding-window attention (fp32, as in R1)
// ---------------------------------------------------------------------------
__global__ __launch_bounds__(256)
void swa_kernel(const float* __restrict__ q, const float* __restrict__ k,
                const float* __restrict__ v, float* __restrict__ out)
{
    __shared__ float4 qs4[DIMC / 4];
    __shared__ float  sc[WIN];

    const int row = blockIdx.x;
    const int b   = row >> 11;
    const int s   = row & (SEQ - 1);
    const int tid = threadIdx.x;
    const int warp = tid >> 5;
    const int lane = tid & 31;
    const float scale = 0.03125f;

    {
        float4 t = ((const float4*)(q + (size_t)row * DIMC))[tid];
        t.x *= scale; t.y *= scale; t.z *= scale; t.w *= scale;
        qs4[tid] = t;
    }
    __syncthreads();

    for (int p = warp; p < WIN; p += 8) {
        const int j = s - HALF + p;
        if (j < 0 || j >= SEQ) {
            if (lane == 0) sc[p] = -__int_as_float(0x7f800000);
            continue;
        }
        const float4* kr = (const float4*)(k + ((size_t)b * SEQ + j) * DIMC);
        float acc = 0.0f;
        for (int c = lane; c < DIMC / 4; c += 32) {
            float4 kv = kr[c];
            float4 qv = qs4[c];
            acc = fmaf(qv.x, kv.x, acc);
            acc = fmaf(qv.y, kv.y, acc);
            acc = fmaf(qv.z, kv.z, acc);
            acc = fmaf(qv.w, kv.w, acc);
        }
        #pragma unroll
        for (int off = 16; off; off >>= 1)
            acc += __shfl_xor_sync(0xffffffffu, acc, off);
        if (lane == 0) sc[p] = acc;
    }
    __syncthreads();

    if (tid < 32) {
        float mx = -__int_as_float(0x7f800000);
        for (int p = tid; p < WIN; p += 32) mx = fmaxf(mx, sc[p]);
        #pragma unroll
        for (int off = 16; off; off >>= 1)
            mx = fmaxf(mx, __shfl_xor_sync(0xffffffffu, mx, off));
        float sum = 0.0f;
        float e[3]; int np = 0;
        for (int p = tid; p < WIN; p += 32) {
            float ev = __expf(sc[p] - mx);
            e[np++] = ev;
            sum += ev;
        }
        #pragma unroll
        for (int off = 16; off; off >>= 1)
            sum += __shfl_xor_sync(0xffffffffu, sum, off);
        float inv = 1.0f / sum;
        np = 0;
        for (int p = tid; p < WIN; p += 32) sc[p] = e[np++] * inv;
    }
    __syncthreads();

    const int j0 = (s - HALF < 0) ? 0 : s - HALF;
    const int j1 = (s + HALF > SEQ - 1) ? SEQ - 1 : s + HALF;
    float4 acc = make_float4(0.f, 0.f, 0.f, 0.f);
    const float4* vb = (const float4*)(v + (size_t)b * SEQ * DIMC);
    for (int j = j0; j <= j1; j++) {
        const float w = sc[j - (s - HALF)];
        float4 vv = vb[(size_t)j * (DIMC / 4) + tid];
        acc.x = fmaf(w, vv.x, acc.x);
        acc.y = fmaf(w, vv.y, acc.y);
        acc.z = fmaf(w, vv.z, acc.z);
        acc.w = fmaf(w, vv.w, acc.w);
    }
    ((float4*)(out + (size_t)row * DIMC))[tid] = acc;
}

// ---------------------------------------------------------------------------
// launch
// ---------------------------------------------------------------------------
extern "C" void kernel_launch(void* const* d_in, const int* in_sizes, int n_in,
                              void* d_out, int out_size)
{
    const float* x     = (const float*)d_in[0];
    const float* nm_w1 = (const float*)d_in[1];
    const float* nm_b1 = (const float*)d_in[2];
    const float* nm_w2 = (const float*)d_in[3];
    const float* nm_b2 = (const float*)d_in[4];
    const float* q_w   = (const float*)d_in[5];
    const float* q_b   = (const float*)d_in[6];
    const float* k_w   = (const float*)d_in[7];
    const float* k_b   = (const float*)d_in[8];
    const float* v_w   = (const float*)d_in[9];
    const float* v_b   = (const float*)d_in[10];
    float* out = (float*)d_out;

    __nv_bfloat16 *x_hi, *x_lo, *h_hi, *h_lo, *m_hi, *m_lo, *w_hi, *w_lo;
    float *q, *k, *v;
    cudaGetSymbolAddress((void**)&x_hi, g_x_hi);
    cudaGetSymbolAddress((void**)&x_lo, g_x_lo);
    cudaGetSymbolAddress((void**)&h_hi, g_h_hi);
    cudaGetSymbolAddress((void**)&h_lo, g_h_lo);
    cudaGetSymbolAddress((void**)&m_hi, g_m_hi);
    cudaGetSymbolAddress((void**)&m_lo, g_m_lo);
    cudaGetSymbolAddress((void**)&w_hi, g_w_hi);
    cudaGetSymbolAddress((void**)&w_lo, g_w_lo);
    cudaGetSymbolAddress((void**)&q, g_q);
    cudaGetSymbolAddress((void**)&k, g_k);
    cudaGetSymbolAddress((void**)&v, g_v);

    cudaFuncSetAttribute(gemm_hmma_kernel<1,0,1>, cudaFuncAttributeMaxDynamicSharedMemorySize, GEMM_SMEM);
    cudaFuncSetAttribute(gemm_hmma_kernel<0,0,1>, cudaFuncAttributeMaxDynamicSharedMemorySize, GEMM_SMEM);
    cudaFuncSetAttribute(gemm_hmma_kernel<0,1,0>, cudaFuncAttributeMaxDynamicSharedMemorySize, GEMM_SMEM);

    constexpr size_t WSZ = (size_t)DIMC * DIMC;

    split_x_kernel<<<(M_TOT * DIMC / 4 + 255) / 256, 256>>>(x, x_hi, x_lo, M_TOT * DIMC / 4);
    dim3 tg(DIMC / 32, DIMC / 32), tb(32, 8);
    transpose_split_kernel<<<tg, tb>>>(nm_w1, w_hi + 0 * WSZ, w_lo + 0 * WSZ);
    transpose_split_kernel<<<tg, tb>>>(nm_w2, w_hi + 1 * WSZ, w_lo + 1 * WSZ);
    transpose_split_kernel<<<tg, tb>>>(q_w,   w_hi + 2 * WSZ, w_lo + 2 * WSZ);
    transpose_split_kernel<<<tg, tb>>>(k_w,   w_hi + 3 * WSZ, w_lo + 3 * WSZ);
    transpose_split_kernel<<<tg, tb>>>(v_w,   w_hi + 4 * WSZ, w_lo + 4 * WSZ);

    dim3 grid(DIMC / 128, M_TOT / 128);   // (8, 32)
    gemm_hmma_kernel<1,0,1><<<grid, 256, GEMM_SMEM>>>(x_hi, x_lo, w_hi + 0 * WSZ, w_lo + 0 * WSZ,
                                                      nm_b1, nullptr, h_hi, h_lo);
    gemm_hmma_kernel<0,0,1><<<grid, 256, GEMM_SMEM>>>(h_hi, h_lo, w_hi + 1 * WSZ, w_lo + 1 * WSZ,
                                                      nm_b2, nullptr, m_hi, m_lo);
    gemm_hmma_kernel<0,1,0><<<grid, 256, GEMM_SMEM>>>(m_hi, m_lo, w_hi + 2 * WSZ, w_lo + 2 * WSZ,
                                                      q_b, q, nullptr, nullptr);
    gemm_hmma_kernel<0,1,0><<<grid, 256, GEMM_SMEM>>>(m_hi, m_lo, w_hi + 3 * WSZ, w_lo + 3 * WSZ,
                                                      k_b, k, nullptr, nullptr);
    gemm_hmma_kernel<0,1,0><<<grid, 256, GEMM_SMEM>>>(m_hi, m_lo, w_hi + 4 * WSZ, w_lo + 4 * WSZ,
                                                      v_b, v, nullptr, nullptr);

    swa_kernel<<<M_TOT, 256>>>(q, k, v, out);
}

// round 4
// speedup vs baseline: 2.0965x; 1.0939x over previous
#include <cuda_runtime.h>
#include <cuda_fp16.h>
#include <cstdint>

// ---------------------------------------------------------------------------
// LongTermMemory, fp16 2-term split HMMA GEMMs + ldmatrix + BK=64.
// A (activations) = Ah + Al (both fp16, ~21-bit effective mantissa);
// B (weights) = fp16 single. D = Ah*B + Al*B in fp32 accum (2 MMAs/tile).
// Error budget: weight rounding ~2.8e-4/layer -> ~4e-4 final (gate 1e-3).
// ---------------------------------------------------------------------------

constexpr int M_TOT = 4096;
constexpr int DIMC  = 1024;
constexpr int SEQ   = 2048;
constexpr int HALF  = 32;
constexpr int WIN   = 65;

// ---------------- scratch ----------------
__device__ __half g_x_hi[M_TOT * DIMC];
__device__ __half g_x_lo[M_TOT * DIMC];
__device__ __half g_h_hi[M_TOT * DIMC];
__device__ __half g_h_lo[M_TOT * DIMC];
__device__ __half g_m_hi[M_TOT * DIMC];
__device__ __half g_m_lo[M_TOT * DIMC];
__device__ float g_q[M_TOT * DIMC];
__device__ float g_k[M_TOT * DIMC];
__device__ float g_v[M_TOT * DIMC];
__device__ __half g_w[5][DIMC * DIMC];   // transposed: Wt[n][k], fp16

// ---------------------------------------------------------------------------
// helpers
// ---------------------------------------------------------------------------
__device__ __forceinline__ uint32_t smem_u32(const void* p) {
    uint32_t a;
    asm("{ .reg .u64 t; cvta.to.shared.u64 t, %1; cvt.u32.u64 %0, t; }"
        : "=r"(a) : "l"(p));
    return a;
}
__device__ __forceinline__ void cp_async16(uint32_t saddr, const void* gaddr) {
    asm volatile("cp.async.cg.shared.global [%0], [%1], 16;"
                 :: "r"(saddr), "l"(gaddr));
}
#define CP_COMMIT()  asm volatile("cp.async.commit_group;" ::: "memory")
#define CP_WAIT(N)   asm volatile("cp.async.wait_group %0;" :: "n"(N) : "memory")

__device__ __forceinline__ void ldmatrix_x4(uint32_t& r0, uint32_t& r1,
                                            uint32_t& r2, uint32_t& r3,
                                            uint32_t addr) {
    asm volatile("ldmatrix.sync.aligned.m8n8.x4.shared.b16 {%0,%1,%2,%3}, [%4];"
                 : "=r"(r0), "=r"(r1), "=r"(r2), "=r"(r3) : "r"(addr));
}

__device__ __forceinline__ void mma16816(float* d, const uint32_t* a,
                                         uint32_t b0, uint32_t b1) {
    asm volatile(
        "mma.sync.aligned.m16n8k16.row.col.f32.f16.f16.f32 "
        "{%0,%1,%2,%3}, {%4,%5,%6,%7}, {%8,%9}, {%0,%1,%2,%3};"
        : "+f"(d[0]), "+f"(d[1]), "+f"(d[2]), "+f"(d[3])
        : "r"(a[0]), "r"(a[1]), "r"(a[2]), "r"(a[3]), "r"(b0), "r"(b1));
}

__device__ __forceinline__ void split_f16(float v, __half& hi, __half& lo) {
    hi = __float2half_rn(v);
    lo = __float2half_rn(v - __half2float(hi));
}

// ---------------------------------------------------------------------------
// conversion kernels
// ---------------------------------------------------------------------------
__global__ void split_x_kernel(const float* __restrict__ x,
                               __half* __restrict__ hi,
                               __half* __restrict__ lo, int n4) {
    int i = blockIdx.x * blockDim.x + threadIdx.x;
    if (i >= n4) return;
    float4 v = ((const float4*)x)[i];
    __half h0, h1, h2, h3, l0, l1, l2, l3;
    split_f16(v.x, h0, l0); split_f16(v.y, h1, l1);
    split_f16(v.z, h2, l2); split_f16(v.w, h3, l3);
    __half2* hp = (__half2*)hi;
    __half2* lp = (__half2*)lo;
    hp[2 * i]     = __halves2half2(h0, h1);
    hp[2 * i + 1] = __halves2half2(h2, h3);
    lp[2 * i]     = __halves2half2(l0, l1);
    lp[2 * i + 1] = __halves2half2(l2, l3);
}

// transpose W[k][n] -> Wt[n][k], fp16
__global__ void transpose_f16_kernel(const float* __restrict__ W,
                                     __half* __restrict__ out) {
    __shared__ float t[32][33];
    const int n0 = blockIdx.x * 32, k0 = blockIdx.y * 32;
    const int tx = threadIdx.x, ty = threadIdx.y;
    #pragma unroll
    for (int i = ty; i < 32; i += 8)
        t[i][tx] = W[(size_t)(k0 + i) * DIMC + n0 + tx];
    __syncthreads();
    #pragma unroll
    for (int i = ty; i < 32; i += 8)
        out[(size_t)(n0 + i) * DIMC + k0 + tx] = __float2half_rn(t[tx][i]);
}

// ---------------------------------------------------------------------------
// HMMA GEMM: C[4096,1024] = (Ah+Al) @ Bt^T + bias
// CTA 128x128, BK=64, 8 warps (2x4), warp 64x32, 2-stage cp.async,
// ldmatrix fragment loads, smem row stride 72 el (conflict-free).
// ---------------------------------------------------------------------------
constexpr int BK = 64;
constexpr int STRIDE = 72;                         // elements
constexpr int TILE_E = 128 * STRIDE;               // 9216 el
constexpr int TILE_B = TILE_E * 2;                 // 18432 B
constexpr int STAGE_B = 3 * TILE_B;                // 55296 B
constexpr int GEMM_SMEM = 2 * STAGE_B;             // 110592 B

template <int RELU, int OUT_F32>
__global__ __launch_bounds__(256, 1)
void gemm_f16_kernel(const __half* __restrict__ A_hi,
                     const __half* __restrict__ A_lo,
                     const __half* __restrict__ B_h,
                     const float* __restrict__ bias,
                     float* __restrict__ Cf,
                     __half* __restrict__ C_hi,
                     __half* __restrict__ C_lo)
{
    extern __shared__ __half sm[];
    const uint32_t sb = smem_u32(sm);

    const int tid  = threadIdx.x;
    const int wid  = tid >> 5;
    const int lane = tid & 31;
    const int bx = blockIdx.x;     // N tile (0..7)
    const int by = blockIdx.y;     // M tile (0..31)

    const int wr = wid >> 2;       // 0..1 -> m offset 64*wr
    const int wc = wid & 3;        // 0..3 -> n offset 32*wc
    const int g   = lane >> 2;
    const int tig = lane & 3;

    // cp.async mapping: thread -> row(tid>>1), 32-el half(tid&1), 4x16B
    const int lrow  = tid >> 1;
    const int lhalf = (tid & 1) * 32;

    const __half* gAh = A_hi + (size_t)(by * 128 + lrow) * DIMC + lhalf;
    const __half* gAl = A_lo + (size_t)(by * 128 + lrow) * DIMC + lhalf;
    const __half* gB  = B_h  + (size_t)(bx * 128 + lrow) * DIMC + lhalf;
    const uint32_t sofs = (lrow * STRIDE + lhalf) * 2;

    auto load_stage = [&](int st, int kt) {
        const uint32_t s0 = sb + st * STAGE_B + sofs;
        const int go = kt * BK;
        #pragma unroll
        for (int c = 0; c < 4; c++) {
            cp_async16(s0 + 0 * TILE_B + c * 16, gAh + go + c * 8);
            cp_async16(s0 + 1 * TILE_B + c * 16, gAl + go + c * 8);
            cp_async16(s0 + 2 * TILE_B + c * 16, gB  + go + c * 8);
        }
    };

    // ldmatrix lane mapping
    const int lr15 = lane & 15;
    const int lk8  = (lane >> 4) << 3;
    // precomputed row offsets (elements) within tile
    const uint32_t aRow = (uint32_t)(wr * 64 + lr15) * STRIDE;
    const uint32_t bRow = (uint32_t)(wc * 32 + lr15) * STRIDE;

    float acc[4][4][4];
    #pragma unroll
    for (int i = 0; i < 4; i++)
        #pragma unroll
        for (int j = 0; j < 4; j++)
            #pragma unroll
            for (int r = 0; r < 4; r++) acc[i][j][r] = 0.0f;

    load_stage(0, 0);
    CP_COMMIT();

    constexpr int NKT = DIMC / BK;   // 16
    for (int kt = 0; kt < NKT; kt++) {
        if (kt + 1 < NKT) {
            load_stage((kt + 1) & 1, kt + 1);
            CP_COMMIT();
            CP_WAIT(1);
        } else {
            CP_WAIT(0);
        }
        __syncthreads();

        const uint32_t st = sb + (kt & 1) * STAGE_B;

        #pragma unroll
        for (int s = 0; s < 4; s++) {
            const uint32_t kc = (uint32_t)(s * 16 + lk8) * 2;
            uint32_t ah[4][4], al[4][4], bf[2][4];
            #pragma unroll
            for (int i = 0; i < 4; i++) {
                const uint32_t ro = (aRow + (uint32_t)(i * 16) * STRIDE) * 2 + kc;
                ldmatrix_x4(ah[i][0], ah[i][1], ah[i][2], ah[i][3], st + ro);
                ldmatrix_x4(al[i][0], al[i][1], al[i][2], al[i][3], st + TILE_B + ro);
            }
            #pragma unroll
            for (int jj = 0; jj < 2; jj++) {
                const uint32_t ro = (bRow + (uint32_t)(jj * 16) * STRIDE) * 2 + kc;
                ldmatrix_x4(bf[jj][0], bf[jj][1], bf[jj][2], bf[jj][3],
                            st + 2 * TILE_B + ro);
            }
            #pragma unroll
            for (int i = 0; i < 4; i++)
                #pragma unroll
                for (int j = 0; j < 4; j++) {
                    const int jj = j >> 1, sel = j & 1;
                    const uint32_t b0 = bf[jj][sel];
                    const uint32_t b1 = bf[jj][sel + 2];
                    mma16816(acc[i][j], ah[i], b0, b1);
                    mma16816(acc[i][j], al[i], b0, b1);
                }
        }
        __syncthreads();
    }

    // ---- epilogue ----
    #pragma unroll
    for (int i = 0; i < 4; i++) {
        const int mg0 = by * 128 + wr * 64 + i * 16 + g;
        #pragma unroll
        for (int j = 0; j < 4; j++) {
            const int ng = bx * 128 + wc * 32 + j * 8 + tig * 2;
            const float b0 = __ldg(bias + ng);
            const float b1 = __ldg(bias + ng + 1);
            float v00 = acc[i][j][0] + b0;
            float v01 = acc[i][j][1] + b1;
            float v10 = acc[i][j][2] + b0;
            float v11 = acc[i][j][3] + b1;
            if (RELU) {
                v00 = fmaxf(v00, 0.0f); v01 = fmaxf(v01, 0.0f);
                v10 = fmaxf(v10, 0.0f); v11 = fmaxf(v11, 0.0f);
            }
            const size_t o0 = (size_t)mg0 * DIMC + ng;
            const size_t o1 = (size_t)(mg0 + 8) * DIMC + ng;
            if (OUT_F32) {
                *(float2*)(Cf + o0) = make_float2(v00, v01);
                *(float2*)(Cf + o1) = make_float2(v10, v11);
            } else {
                __half h0, l0, h1, l1;
                split_f16(v00, h0, l0); split_f16(v01, h1, l1);
                *(__half2*)(C_hi + o0) = __halves2half2(h0, h1);
                *(__half2*)(C_lo + o0) = __halves2half2(l0, l1);
                split_f16(v10, h0, l0); split_f16(v11, h1, l1);
                *(__half2*)(C_hi + o1) = __halves2half2(h0, h1);
                *(__half2*)(C_lo + o1) = __halves2half2(l0, l1);
            }
        }
    }
}

// ---------------------------------------------------------------------------
// Sliding-window attention (fp32)
// ---------------------------------------------------------------------------
__global__ __launch_bounds__(256)
void swa_kernel(const float* __restrict__ q, const float* __restrict__ k,
                const float* __restrict__ v, float* __restrict__ out)
{
    __shared__ float4 qs4[DIMC / 4];
    __shared__ float  sc[WIN];

    const int row = blockIdx.x;
    const int b   = row >> 11;
    const int s   = row & (SEQ - 1);
    const int tid = threadIdx.x;
    const int warp = tid >> 5;
    const int lane = tid & 31;
    const float scale = 0.03125f;

    {
        float4 t = ((const float4*)(q + (size_t)row * DIMC))[tid];
        t.x *= scale; t.y *= scale; t.z *= scale; t.w *= scale;
        qs4[tid] = t;
    }
    __syncthreads();

    for (int p = warp; p < WIN; p += 8) {
        const int j = s - HALF + p;
        if (j < 0 || j >= SEQ) {
            if (lane == 0) sc[p] = -__int_as_float(0x7f800000);
            continue;
        }
        const float4* kr = (const float4*)(k + ((size_t)b * SEQ + j) * DIMC);
        float acc = 0.0f;
        for (int c = lane; c < DIMC / 4; c += 32) {
            float4 kv = kr[c];
            float4 qv = qs4[c];
            acc = fmaf(qv.x, kv.x, acc);
            acc = fmaf(qv.y, kv.y, acc);
            acc = fmaf(qv.z, kv.z, acc);
            acc = fmaf(qv.w, kv.w, acc);
        }
        #pragma unroll
        for (int off = 16; off; off >>= 1)
            acc += __shfl_xor_sync(0xffffffffu, acc, off);
        if (lane == 0) sc[p] = acc;
    }
    __syncthreads();

    if (tid < 32) {
        float mx = -__int_as_float(0x7f800000);
        for (int p = tid; p < WIN; p += 32) mx = fmaxf(mx, sc[p]);
        #pragma unroll
        for (int off = 16; off; off >>= 1)
            mx = fmaxf(mx, __shfl_xor_sync(0xffffffffu, mx, off));
        float sum = 0.0f;
        float e[3]; int np = 0;
        for (int p = tid; p < WIN; p += 32) {
            float ev = __expf(sc[p] - mx);
            e[np++] = ev;
            sum += ev;
        }
        #pragma unroll
        for (int off = 16; off; off >>= 1)
            sum += __shfl_xor_sync(0xffffffffu, sum, off);
        float inv = 1.0f / sum;
        np = 0;
        for (int p = tid; p < WIN; p += 32) sc[p] = e[np++] * inv;
    }
    __syncthreads();

    const int j0 = (s - HALF < 0) ? 0 : s - HALF;
    const int j1 = (s + HALF > SEQ - 1) ? SEQ - 1 : s + HALF;
    float4 acc = make_float4(0.f, 0.f, 0.f, 0.f);
    const float4* vb = (const float4*)(v + (size_t)b * SEQ * DIMC);
    for (int j = j0; j <= j1; j++) {
        const float w = sc[j - (s - HALF)];
        float4 vv = vb[(size_t)j * (DIMC / 4) + tid];
        acc.x = fmaf(w, vv.x, acc.x);
        acc.y = fmaf(w, vv.y, acc.y);
        acc.z = fmaf(w, vv.z, acc.z);
        acc.w = fmaf(w, vv.w, acc.w);
    }
    ((float4*)(out + (size_t)row * DIMC))[tid] = acc;
}

// ---------------------------------------------------------------------------
// launch
// ---------------------------------------------------------------------------
extern "C" void kernel_launch(void* const* d_in, const int* in_sizes, int n_in,
                              void* d_out, int out_size)
{
    const float* x     = (const float*)d_in[0];
    const float* nm_w1 = (const float*)d_in[1];
    const float* nm_b1 = (const float*)d_in[2];
    const float* nm_w2 = (const float*)d_in[3];
    const float* nm_b2 = (const float*)d_in[4];
    const float* q_w   = (const float*)d_in[5];
    const float* q_b   = (const float*)d_in[6];
    const float* k_w   = (const float*)d_in[7];
    const float* k_b   = (const float*)d_in[8];
    const float* v_w   = (const float*)d_in[9];
    const float* v_b   = (const float*)d_in[10];
    float* out = (float*)d_out;

    __half *x_hi, *x_lo, *h_hi, *h_lo, *m_hi, *m_lo, *w;
    float *q, *k, *v;
    cudaGetSymbolAddress((void**)&x_hi, g_x_hi);
    cudaGetSymbolAddress((void**)&x_lo, g_x_lo);
    cudaGetSymbolAddress((void**)&h_hi, g_h_hi);
    cudaGetSymbolAddress((void**)&h_lo, g_h_lo);
    cudaGetSymbolAddress((void**)&m_hi, g_m_hi);
    cudaGetSymbolAddress((void**)&m_lo, g_m_lo);
    cudaGetSymbolAddress((void**)&w, g_w);
    cudaGetSymbolAddress((void**)&q, g_q);
    cudaGetSymbolAddress((void**)&k, g_k);
    cudaGetSymbolAddress((void**)&v, g_v);

    cudaFuncSetAttribute(gemm_f16_kernel<1,0>, cudaFuncAttributeMaxDynamicSharedMemorySize, GEMM_SMEM);
    cudaFuncSetAttribute(gemm_f16_kernel<0,0>, cudaFuncAttributeMaxDynamicSharedMemorySize, GEMM_SMEM);
    cudaFuncSetAttribute(gemm_f16_kernel<0,1>, cudaFuncAttributeMaxDynamicSharedMemorySize, GEMM_SMEM);

    constexpr size_t WSZ = (size_t)DIMC * DIMC;

    split_x_kernel<<<(M_TOT * DIMC / 4 + 255) / 256, 256>>>(x, x_hi, x_lo, M_TOT * DIMC / 4);
    dim3 tg(DIMC / 32, DIMC / 32), tb(32, 8);
    transpose_f16_kernel<<<tg, tb>>>(nm_w1, w + 0 * WSZ);
    transpose_f16_kernel<<<tg, tb>>>(nm_w2, w + 1 * WSZ);
    transpose_f16_kernel<<<tg, tb>>>(q_w,   w + 2 * WSZ);
    transpose_f16_kernel<<<tg, tb>>>(k_w,   w + 3 * WSZ);
    transpose_f16_kernel<<<tg, tb>>>(v_w,   w + 4 * WSZ);

    dim3 grid(DIMC / 128, M_TOT / 128);   // (8, 32)
    gemm_f16_kernel<1,0><<<grid, 256, GEMM_SMEM>>>(x_hi, x_lo, w + 0 * WSZ,
                                                   nm_b1, nullptr, h_hi, h_lo);
    gemm_f16_kernel<0,0><<<grid, 256, GEMM_SMEM>>>(h_hi, h_lo, w + 1 * WSZ,
                                                   nm_b2, nullptr, m_hi, m_lo);
    gemm_f16_kernel<0,1><<<grid, 256, GEMM_SMEM>>>(m_hi, m_lo, w + 2 * WSZ,
                                                   q_b, q, nullptr, nullptr);
    gemm_f16_kernel<0,1><<<grid, 256, GEMM_SMEM>>>(m_hi, m_lo, w + 3 * WSZ,
                                                   k_b, k, nullptr, nullptr);
    gemm_f16_kernel<0,1><<<grid, 256, GEMM_SMEM>>>(m_hi, m_lo, w + 4 * WSZ,
                                                   v_b, v, nullptr, nullptr);

    swa_kernel<<<M_TOT, 256>>>(q, k, v, out);
}

// round 5
// speedup vs baseline: 3.1847x; 1.5190x over previous
#include <cuda_runtime.h>
#include <cuda_fp16.h>
#include <cstdint>

// ---------------------------------------------------------------------------
// LongTermMemory: plain fp16 HMMA GEMMs (1 MMA/tile), 2 CTAs/SM, ldmatrix.
// Error model (calibrated R3/R4): W+A fp16 rounding ~4e-4/layer, attention
// attenuation ~0.5x -> predicted rel_err ~4.5e-4 (gate 1e-3).
// ---------------------------------------------------------------------------

constexpr int M_TOT = 4096;
constexpr int DIMC  = 1024;
constexpr int SEQ   = 2048;
constexpr int HALF  = 32;
constexpr int WIN   = 65;

// ---------------- scratch ----------------
__device__ __half g_xh[M_TOT * DIMC];
__device__ __half g_h[M_TOT * DIMC];
__device__ __half g_m[M_TOT * DIMC];
__device__ float g_q[M_TOT * DIMC];
__device__ float g_k[M_TOT * DIMC];
__device__ float g_v[M_TOT * DIMC];
__device__ __half g_w[5][DIMC * DIMC];   // transposed: Wt[n][k], fp16

// ---------------------------------------------------------------------------
// helpers
// ---------------------------------------------------------------------------
__device__ __forceinline__ uint32_t smem_u32(const void* p) {
    uint32_t a;
    asm("{ .reg .u64 t; cvta.to.shared.u64 t, %1; cvt.u32.u64 %0, t; }"
        : "=r"(a) : "l"(p));
    return a;
}
__device__ __forceinline__ void cp_async16(uint32_t saddr, const void* gaddr) {
    asm volatile("cp.async.cg.shared.global [%0], [%1], 16;"
                 :: "r"(saddr), "l"(gaddr));
}
#define CP_COMMIT()  asm volatile("cp.async.commit_group;" ::: "memory")
#define CP_WAIT(N)   asm volatile("cp.async.wait_group %0;" :: "n"(N) : "memory")

__device__ __forceinline__ void ldmatrix_x4(uint32_t& r0, uint32_t& r1,
                                            uint32_t& r2, uint32_t& r3,
                                            uint32_t addr) {
    asm volatile("ldmatrix.sync.aligned.m8n8.x4.shared.b16 {%0,%1,%2,%3}, [%4];"
                 : "=r"(r0), "=r"(r1), "=r"(r2), "=r"(r3) : "r"(addr));
}

__device__ __forceinline__ void mma16816(float* d, const uint32_t* a,
                                         uint32_t b0, uint32_t b1) {
    asm volatile(
        "mma.sync.aligned.m16n8k16.row.col.f32.f16.f16.f32 "
        "{%0,%1,%2,%3}, {%4,%5,%6,%7}, {%8,%9}, {%0,%1,%2,%3};"
        : "+f"(d[0]), "+f"(d[1]), "+f"(d[2]), "+f"(d[3])
        : "r"(a[0]), "r"(a[1]), "r"(a[2]), "r"(a[3]), "r"(b0), "r"(b1));
}

// ---------------------------------------------------------------------------
// prep kernel: one launch does x->fp16 convert + all 5 weight transposes.
// blocks 0..4095: x tiles (128 x 32 grid of 32x32). blocks 4096..9215:
// weight transpose tiles (5 x 1024).
// ---------------------------------------------------------------------------
__global__ __launch_bounds__(256)
void prep_kernel(const float* __restrict__ x,
                 const float* __restrict__ w1, const float* __restrict__ w2,
                 const float* __restrict__ qw, const float* __restrict__ kw,
                 const float* __restrict__ vw,
                 __half* __restrict__ xh, __half* __restrict__ wt)
{
    const int b = blockIdx.x;
    const int tid = threadIdx.x;
    if (b < 4096) {
        // x convert: tile (row0, col0) 32x32
        const int row0 = (b >> 5) << 5;
        const int col0 = (b & 31) << 5;
        const int r = tid >> 3;               // 0..31
        const int c = (tid & 7) << 2;         // 0..28 step 4
        const size_t o = (size_t)(row0 + r) * DIMC + col0 + c;
        float4 v = *(const float4*)(x + o);
        __half2* hp = (__half2*)(xh + o);
        hp[0] = __floats2half2_rn(v.x, v.y);
        hp[1] = __floats2half2_rn(v.z, v.w);
    } else {
        __shared__ float t[32][33];
        const int wb = b - 4096;
        const int wi = wb >> 10;              // 0..4
        const int within = wb & 1023;
        const int n0 = (within & 31) << 5;
        const int k0 = (within >> 5) << 5;
        const float* W = (wi == 0) ? w1 : (wi == 1) ? w2 :
                         (wi == 2) ? qw : (wi == 3) ? kw : vw;
        __half* out = wt + (size_t)wi * DIMC * DIMC;
        const int tx = tid & 31, ty = tid >> 5;   // 32 x 8
        #pragma unroll
        for (int i = ty; i < 32; i += 8)
            t[i][tx] = W[(size_t)(k0 + i) * DIMC + n0 + tx];
        __syncthreads();
        #pragma unroll
        for (int i = ty; i < 32; i += 8)
            out[(size_t)(n0 + i) * DIMC + k0 + tx] = __float2half_rn(t[tx][i]);
    }
}

// ---------------------------------------------------------------------------
// HMMA GEMM: C[4096,1024] = A @ Bt^T + bias  (A [m][k] fp16, Bt [n][k] fp16)
// CTA 128x128, BK=64, 8 warps (2x4), warp 64x32, 2-stage cp.async,
// ldmatrix, stride 72 el (conflict-free). 2 CTAs/SM (73.7KB smem).
// ---------------------------------------------------------------------------
constexpr int BK = 64;
constexpr int STRIDE = 72;                         // elements
constexpr int TILE_E = 128 * STRIDE;               // 9216 el
constexpr int TILE_B = TILE_E * 2;                 // 18432 B
constexpr int STAGE_B = 2 * TILE_B;                // 36864 B (A + B)
constexpr int GEMM_SMEM = 2 * STAGE_B;             // 73728 B

template <int RELU, int OUT_F32>
__global__ __launch_bounds__(256, 2)
void gemm_f16_kernel(const __half* __restrict__ A_h,
                     const __half* __restrict__ B_h,
                     const float* __restrict__ bias,
                     float* __restrict__ Cf,
                     __half* __restrict__ Ch)
{
    extern __shared__ __half sm[];
    const uint32_t sb = smem_u32(sm);

    const int tid  = threadIdx.x;
    const int wid  = tid >> 5;
    const int lane = tid & 31;
    const int bx = blockIdx.x;     // N tile (0..7)
    const int by = blockIdx.y;     // M tile (0..31)

    const int wr = wid >> 2;       // 0..1 -> m offset 64*wr
    const int wc = wid & 3;        // 0..3 -> n offset 32*wc
    const int g   = lane >> 2;
    const int tig = lane & 3;

    // cp.async mapping: thread -> row(tid>>1), 32-el half(tid&1)
    const int lrow  = tid >> 1;
    const int lhalf = (tid & 1) * 32;

    const __half* gA = A_h + (size_t)(by * 128 + lrow) * DIMC + lhalf;
    const __half* gB = B_h + (size_t)(bx * 128 + lrow) * DIMC + lhalf;
    const uint32_t sofs = (lrow * STRIDE + lhalf) * 2;

    auto load_stage = [&](int st, int kt) {
        const uint32_t s0 = sb + st * STAGE_B + sofs;
        const int go = kt * BK;
        #pragma unroll
        for (int c = 0; c < 4; c++) {
            cp_async16(s0 + c * 16, gA + go + c * 8);
            cp_async16(s0 + TILE_B + c * 16, gB + go + c * 8);
        }
    };

    // ldmatrix lane mapping
    const int lr15 = lane & 15;
    const int lk8  = (lane >> 4) << 3;
    const uint32_t aRow = (uint32_t)(wr * 64 + lr15) * STRIDE;
    const uint32_t bRow = (uint32_t)(wc * 32 + lr15) * STRIDE;

    float acc[4][4][4];
    #pragma unroll
    for (int i = 0; i < 4; i++)
        #pragma unroll
        for (int j = 0; j < 4; j++)
            #pragma unroll
            for (int r = 0; r < 4; r++) acc[i][j][r] = 0.0f;

    load_stage(0, 0);
    CP_COMMIT();

    constexpr int NKT = DIMC / BK;   // 16
    for (int kt = 0; kt < NKT; kt++) {
        if (kt + 1 < NKT) {
            load_stage((kt + 1) & 1, kt + 1);
            CP_COMMIT();
            CP_WAIT(1);
        } else {
            CP_WAIT(0);
        }
        __syncthreads();

        const uint32_t st = sb + (kt & 1) * STAGE_B;

        #pragma unroll
        for (int s = 0; s < 4; s++) {
            const uint32_t kc = (uint32_t)(s * 16 + lk8) * 2;
            uint32_t ah[4][4], bf[2][4];
            #pragma unroll
            for (int i = 0; i < 4; i++) {
                const uint32_t ro = (aRow + (uint32_t)(i * 16) * STRIDE) * 2 + kc;
                ldmatrix_x4(ah[i][0], ah[i][1], ah[i][2], ah[i][3], st + ro);
            }
            #pragma unroll
            for (int jj = 0; jj < 2; jj++) {
                const uint32_t ro = (bRow + (uint32_t)(jj * 16) * STRIDE) * 2 + kc;
                ldmatrix_x4(bf[jj][0], bf[jj][1], bf[jj][2], bf[jj][3],
                            st + TILE_B + ro);
            }
            #pragma unroll
            for (int i = 0; i < 4; i++)
                #pragma unroll
                for (int j = 0; j < 4; j++) {
                    const int jj = j >> 1, sel = j & 1;
                    mma16816(acc[i][j], ah[i], bf[jj][sel], bf[jj][sel + 2]);
                }
        }
        __syncthreads();
    }

    // ---- epilogue ----
    #pragma unroll
    for (int i = 0; i < 4; i++) {
        const int mg0 = by * 128 + wr * 64 + i * 16 + g;
        #pragma unroll
        for (int j = 0; j < 4; j++) {
            const int ng = bx * 128 + wc * 32 + j * 8 + tig * 2;
            const float b0 = __ldg(bias + ng);
            const float b1 = __ldg(bias + ng + 1);
            float v00 = acc[i][j][0] + b0;
            float v01 = acc[i][j][1] + b1;
            float v10 = acc[i][j][2] + b0;
            float v11 = acc[i][j][3] + b1;
            if (RELU) {
                v00 = fmaxf(v00, 0.0f); v01 = fmaxf(v01, 0.0f);
                v10 = fmaxf(v10, 0.0f); v11 = fmaxf(v11, 0.0f);
            }
            const size_t o0 = (size_t)mg0 * DIMC + ng;
            const size_t o1 = (size_t)(mg0 + 8) * DIMC + ng;
            if (OUT_F32) {
                *(float2*)(Cf + o0) = make_float2(v00, v01);
                *(float2*)(Cf + o1) = make_float2(v10, v11);
            } else {
                *(__half2*)(Ch + o0) = __floats2half2_rn(v00, v01);
                *(__half2*)(Ch + o1) = __floats2half2_rn(v10, v11);
            }
        }
    }
}

// ---------------------------------------------------------------------------
// Sliding-window attention (fp32)
// ---------------------------------------------------------------------------
__global__ __launch_bounds__(256)
void swa_kernel(const float* __restrict__ q, const float* __restrict__ k,
                const float* __restrict__ v, float* __restrict__ out)
{
    __shared__ float4 qs4[DIMC / 4];
    __shared__ float  sc[WIN];

    const int row = blockIdx.x;
    const int b   = row >> 11;
    const int s   = row & (SEQ - 1);
    const int tid = threadIdx.x;
    const int warp = tid >> 5;
    const int lane = tid & 31;
    const float scale = 0.03125f;

    {
        float4 t = ((const float4*)(q + (size_t)row * DIMC))[tid];
        t.x *= scale; t.y *= scale; t.z *= scale; t.w *= scale;
        qs4[tid] = t;
    }
    __syncthreads();

    for (int p = warp; p < WIN; p += 8) {
        const int j = s - HALF + p;
        if (j < 0 || j >= SEQ) {
            if (lane == 0) sc[p] = -__int_as_float(0x7f800000);
            continue;
        }
        const float4* kr = (const float4*)(k + ((size_t)b * SEQ + j) * DIMC);
        float acc = 0.0f;
        for (int c = lane; c < DIMC / 4; c += 32) {
            float4 kv = kr[c];
            float4 qv = qs4[c];
            acc = fmaf(qv.x, kv.x, acc);
            acc = fmaf(qv.y, kv.y, acc);
            acc = fmaf(qv.z, kv.z, acc);
            acc = fmaf(qv.w, kv.w, acc);
        }
        #pragma unroll
        for (int off = 16; off; off >>= 1)
            acc += __shfl_xor_sync(0xffffffffu, acc, off);
        if (lane == 0) sc[p] = acc;
    }
    __syncthreads();

    if (tid < 32) {
        float mx = -__int_as_float(0x7f800000);
        for (int p = tid; p < WIN; p += 32) mx = fmaxf(mx, sc[p]);
        #pragma unroll
        for (int off = 16; off; off >>= 1)
            mx = fmaxf(mx, __shfl_xor_sync(0xffffffffu, mx, off));
        float sum = 0.0f;
        float e[3]; int np = 0;
        for (int p = tid; p < WIN; p += 32) {
            float ev = __expf(sc[p] - mx);
            e[np++] = ev;
            sum += ev;
        }
        #pragma unroll
        for (int off = 16; off; off >>= 1)
            sum += __shfl_xor_sync(0xffffffffu, sum, off);
        float inv = 1.0f / sum;
        np = 0;
        for (int p = tid; p < WIN; p += 32) sc[p] = e[np++] * inv;
    }
    __syncthreads();

    const int j0 = (s - HALF < 0) ? 0 : s - HALF;
    const int j1 = (s + HALF > SEQ - 1) ? SEQ - 1 : s + HALF;
    float4 acc = make_float4(0.f, 0.f, 0.f, 0.f);
    const float4* vb = (const float4*)(v + (size_t)b * SEQ * DIMC);
    for (int j = j0; j <= j1; j++) {
        const float w = sc[j - (s - HALF)];
        float4 vv = vb[(size_t)j * (DIMC / 4) + tid];
        acc.x = fmaf(w, vv.x, acc.x);
        acc.y = fmaf(w, vv.y, acc.y);
        acc.z = fmaf(w, vv.z, acc.z);
        acc.w = fmaf(w, vv.w, acc.w);
    }
    ((float4*)(out + (size_t)row * DIMC))[tid] = acc;
}

// ---------------------------------------------------------------------------
// launch  (order matters: ncu -s 5 -c 1 captures launch #6 = V GEMM)
// ---------------------------------------------------------------------------
extern "C" void kernel_launch(void* const* d_in, const int* in_sizes, int n_in,
                              void* d_out, int out_size)
{
    const float* x     = (const float*)d_in[0];
    const float* nm_w1 = (const float*)d_in[1];
    const float* nm_b1 = (const float*)d_in[2];
    const float* nm_w2 = (const float*)d_in[3];
    const float* nm_b2 = (const float*)d_in[4];
    const float* q_w   = (const float*)d_in[5];
    const float* q_b   = (const float*)d_in[6];
    const float* k_w   = (const float*)d_in[7];
    const float* k_b   = (const float*)d_in[8];
    const float* v_w   = (const float*)d_in[9];
    const float* v_b   = (const float*)d_in[10];
    float* out = (float*)d_out;

    __half *xh, *h, *m, *w;
    float *q, *k, *v;
    cudaGetSymbolAddress((void**)&xh, g_xh);
    cudaGetSymbolAddress((void**)&h, g_h);
    cudaGetSymbolAddress((void**)&m, g_m);
    cudaGetSymbolAddress((void**)&w, g_w);
    cudaGetSymbolAddress((void**)&q, g_q);
    cudaGetSymbolAddress((void**)&k, g_k);
    cudaGetSymbolAddress((void**)&v, g_v);

    cudaFuncSetAttribute(gemm_f16_kernel<1,0>, cudaFuncAttributeMaxDynamicSharedMemorySize, GEMM_SMEM);
    cudaFuncSetAttribute(gemm_f16_kernel<0,0>, cudaFuncAttributeMaxDynamicSharedMemorySize, GEMM_SMEM);
    cudaFuncSetAttribute(gemm_f16_kernel<0,1>, cudaFuncAttributeMaxDynamicSharedMemorySize, GEMM_SMEM);

    constexpr size_t WSZ = (size_t)DIMC * DIMC;

    // launch 1: all conversions fused
    prep_kernel<<<4096 + 5 * 1024, 256>>>(x, nm_w1, nm_w2, q_w, k_w, v_w, xh, w);

    dim3 grid(DIMC / 128, M_TOT / 128);   // (8, 32)
    // launches 2..6
    gemm_f16_kernel<1,0><<<grid, 256, GEMM_SMEM>>>(xh, w + 0 * WSZ, nm_b1, nullptr, h);
    gemm_f16_kernel<0,0><<<grid, 256, GEMM_SMEM>>>(h,  w + 1 * WSZ, nm_b2, nullptr, m);
    gemm_f16_kernel<0,1><<<grid, 256, GEMM_SMEM>>>(m,  w + 2 * WSZ, q_b, q, nullptr);
    gemm_f16_kernel<0,1><<<grid, 256, GEMM_SMEM>>>(m,  w + 3 * WSZ, k_b, k, nullptr);
    gemm_f16_kernel<0,1><<<grid, 256, GEMM_SMEM>>>(m,  w + 4 * WSZ, v_b, v, nullptr);  // <- ncu capture

    // launch 7
    swa_kernel<<<M_TOT, 256>>>(q, k, v, out);
}

// round 6
// speedup vs baseline: 3.6105x; 1.1337x over previous
#include <cuda_runtime.h>
#include <cuda_fp16.h>
#include <cstdint>

// ---------------------------------------------------------------------------
// LongTermMemory: fp16 HMMA GEMMs, 3-stage cp.async (BK=32), one sync/kt,
// batched ldmatrix, QKV fused into one launch. swa fp32 (unchanged).
// ---------------------------------------------------------------------------

constexpr int M_TOT = 4096;
constexpr int DIMC  = 1024;
constexpr int SEQ   = 2048;
constexpr int HALF  = 32;
constexpr int WIN   = 65;

// ---------------- scratch ----------------
__device__ __half g_xh[M_TOT * DIMC];
__device__ __half g_h[M_TOT * DIMC];
__device__ __half g_m[M_TOT * DIMC];
__device__ float g_qkv[3][M_TOT * DIMC];
__device__ float g_bqkv[3 * DIMC];
__device__ __half g_w[5][DIMC * DIMC];   // transposed: Wt[n][k], fp16

// ---------------------------------------------------------------------------
// helpers
// ---------------------------------------------------------------------------
__device__ __forceinline__ uint32_t smem_u32(const void* p) {
    uint32_t a;
    asm("{ .reg .u64 t; cvta.to.shared.u64 t, %1; cvt.u32.u64 %0, t; }"
        : "=r"(a) : "l"(p));
    return a;
}
__device__ __forceinline__ void cp_async16(uint32_t saddr, const void* gaddr) {
    asm volatile("cp.async.cg.shared.global [%0], [%1], 16;"
                 :: "r"(saddr), "l"(gaddr));
}
#define CP_COMMIT()  asm volatile("cp.async.commit_group;" ::: "memory")
#define CP_WAIT(N)   asm volatile("cp.async.wait_group %0;" :: "n"(N) : "memory")

__device__ __forceinline__ void ldmatrix_x4(uint32_t& r0, uint32_t& r1,
                                            uint32_t& r2, uint32_t& r3,
                                            uint32_t addr) {
    asm volatile("ldmatrix.sync.aligned.m8n8.x4.shared.b16 {%0,%1,%2,%3}, [%4];"
                 : "=r"(r0), "=r"(r1), "=r"(r2), "=r"(r3) : "r"(addr));
}

__device__ __forceinline__ void mma16816(float* d, const uint32_t* a,
                                         uint32_t b0, uint32_t b1) {
    asm volatile(
        "mma.sync.aligned.m16n8k16.row.col.f32.f16.f16.f32 "
        "{%0,%1,%2,%3}, {%4,%5,%6,%7}, {%8,%9}, {%0,%1,%2,%3};"
        : "+f"(d[0]), "+f"(d[1]), "+f"(d[2]), "+f"(d[3])
        : "r"(a[0]), "r"(a[1]), "r"(a[2]), "r"(a[3]), "r"(b0), "r"(b1));
}

// ---------------------------------------------------------------------------
// prep kernel: x->fp16, 5 weight transposes, qkv bias concat.
// ---------------------------------------------------------------------------
__global__ __launch_bounds__(256)
void prep_kernel(const float* __restrict__ x,
                 const float* __restrict__ w1, const float* __restrict__ w2,
                 const float* __restrict__ qw, const float* __restrict__ kw,
                 const float* __restrict__ vw,
                 const float* __restrict__ qb, const float* __restrict__ kb,
                 const float* __restrict__ vb,
                 __half* __restrict__ xh, __half* __restrict__ wt,
                 float* __restrict__ bqkv)
{
    const int b = blockIdx.x;
    const int tid = threadIdx.x;
    if (b < 4096) {
        const int row0 = (b >> 5) << 5;
        const int col0 = (b & 31) << 5;
        const int r = tid >> 3;
        const int c = (tid & 7) << 2;
        const size_t o = (size_t)(row0 + r) * DIMC + col0 + c;
        float4 v = *(const float4*)(x + o);
        __half2* hp = (__half2*)(xh + o);
        hp[0] = __floats2half2_rn(v.x, v.y);
        hp[1] = __floats2half2_rn(v.z, v.w);
    } else if (b < 4096 + 5120) {
        __shared__ float t[32][33];
        const int wb = b - 4096;
        const int wi = wb >> 10;
        const int within = wb & 1023;
        const int n0 = (within & 31) << 5;
        const int k0 = (within >> 5) << 5;
        const float* W = (wi == 0) ? w1 : (wi == 1) ? w2 :
                         (wi == 2) ? qw : (wi == 3) ? kw : vw;
        __half* out = wt + (size_t)wi * DIMC * DIMC;
        const int tx = tid & 31, ty = tid >> 5;
        #pragma unroll
        for (int i = ty; i < 32; i += 8)
            t[i][tx] = W[(size_t)(k0 + i) * DIMC + n0 + tx];
        __syncthreads();
        #pragma unroll
        for (int i = ty; i < 32; i += 8)
            out[(size_t)(n0 + i) * DIMC + k0 + tx] = __float2half_rn(t[tx][i]);
    } else {
        for (int i = tid; i < DIMC; i += 256) {
            bqkv[i]            = qb[i];
            bqkv[DIMC + i]     = kb[i];
            bqkv[2 * DIMC + i] = vb[i];
        }
    }
}

// ---------------------------------------------------------------------------
// HMMA GEMM: CTA 128x128, BK=32, 3-stage cp.async, one sync/kt, 2 CTAs/SM.
// NSTACK>1: grid.x = 8*NSTACK, stacked B/bias/out selected by bx>>3.
// ---------------------------------------------------------------------------
constexpr int BK = 32;
constexpr int STRIDE = 40;                        // elements (32 + 8 pad)
constexpr int TILE_E = 128 * STRIDE;              // 5120 el
constexpr int TILE_B = TILE_E * 2;                // 10240 B
constexpr int STAGE_B = 2 * TILE_B;               // 20480 B (A + B)
constexpr int GEMM_SMEM = 3 * STAGE_B;            // 61440 B

template <int RELU, int OUT_F32, int NSTACK>
__global__ __launch_bounds__(256, 2)
void gemm_f16_kernel(const __half* __restrict__ A_h,
                     const __half* __restrict__ B_base,
                     const float* __restrict__ bias_base,
                     float* __restrict__ Cf_base,
                     __half* __restrict__ Ch)
{
    extern __shared__ __half sm[];
    const uint32_t sb = smem_u32(sm);

    const int tid  = threadIdx.x;
    const int wid  = tid >> 5;
    const int lane = tid & 31;
    int bx = blockIdx.x;
    const int by = blockIdx.y;
    int wsel = 0;
    if (NSTACK > 1) { wsel = bx >> 3; bx &= 7; }

    const __half* B   = B_base + (size_t)wsel * DIMC * DIMC;
    const float* bias = bias_base + wsel * DIMC;
    float* Cf = OUT_F32 ? (Cf_base + (size_t)wsel * M_TOT * DIMC) : nullptr;

    const int wr = wid >> 2;
    const int wc = wid & 3;
    const int g   = lane >> 2;
    const int tig = lane & 3;

    // cp.async mapping: row = tid>>1, 16-el half = tid&1
    const int lrow = tid >> 1;
    const int lsel = (tid & 1) * 16;

    const __half* gA = A_h + (size_t)(by * 128 + lrow) * DIMC + lsel;
    const __half* gB = B   + (size_t)(bx * 128 + lrow) * DIMC + lsel;
    const uint32_t sofs = (lrow * STRIDE + lsel) * 2;

    auto load_stage = [&](int buf, int kt) {
        const uint32_t s0 = sb + buf * STAGE_B + sofs;
        const int go = kt * BK;
        cp_async16(s0,               gA + go);
        cp_async16(s0 + 16,          gA + go + 8);
        cp_async16(s0 + TILE_B,      gB + go);
        cp_async16(s0 + TILE_B + 16, gB + go + 8);
    };

    // ldmatrix lane mapping
    const int lr15 = lane & 15;
    const int lk8  = (lane >> 4) << 3;
    const uint32_t aBase = ((uint32_t)(wr * 64 + lr15) * STRIDE + lk8) * 2;
    const uint32_t bBase = ((uint32_t)(wc * 32 + lr15) * STRIDE + lk8) * 2 + TILE_B;

    float acc[4][4][4];
    #pragma unroll
    for (int i = 0; i < 4; i++)
        #pragma unroll
        for (int j = 0; j < 4; j++)
            #pragma unroll
            for (int r = 0; r < 4; r++) acc[i][j][r] = 0.0f;

    load_stage(0, 0); CP_COMMIT();
    load_stage(1, 1); CP_COMMIT();

    constexpr int NKT = DIMC / BK;   // 32
    int buf = 0;
    for (int kt = 0; kt < NKT; kt++) {
        CP_WAIT(1);
        __syncthreads();
        // issue next-next stage into the buffer everyone finished last iter
        if (kt + 2 < NKT) {
            int nb = buf + 2; if (nb >= 3) nb -= 3;
            load_stage(nb, kt + 2);
        }
        CP_COMMIT();

        const uint32_t st = sb + buf * STAGE_B;

        // batch-load all fragments for both k16 steps
        uint32_t ah[2][4][4], bf[2][2][4];
        #pragma unroll
        for (int s = 0; s < 2; s++) {
            const uint32_t kc = (uint32_t)(s * 16) * 2;
            #pragma unroll
            for (int i = 0; i < 4; i++) {
                const uint32_t ro = st + aBase + (uint32_t)(i * 16 * STRIDE) * 2 + kc;
                ldmatrix_x4(ah[s][i][0], ah[s][i][1], ah[s][i][2], ah[s][i][3], ro);
            }
            #pragma unroll
            for (int jj = 0; jj < 2; jj++) {
                const uint32_t ro = st + bBase + (uint32_t)(jj * 16 * STRIDE) * 2 + kc;
                ldmatrix_x4(bf[s][jj][0], bf[s][jj][1], bf[s][jj][2], bf[s][jj][3], ro);
            }
        }
        #pragma unroll
        for (int s = 0; s < 2; s++)
            #pragma unroll
            for (int i = 0; i < 4; i++)
                #pragma unroll
                for (int j = 0; j < 4; j++) {
                    const int jj = j >> 1, sel = j & 1;
                    mma16816(acc[i][j], ah[s][i], bf[s][jj][sel], bf[s][jj][sel + 2]);
                }

        if (++buf == 3) buf = 0;
    }

    // ---- epilogue ----
    #pragma unroll
    for (int i = 0; i < 4; i++) {
        const int mg0 = by * 128 + wr * 64 + i * 16 + g;
        #pragma unroll
        for (int j = 0; j < 4; j++) {
            const int ng = bx * 128 + wc * 32 + j * 8 + tig * 2;
            const float b0 = __ldg(bias + ng);
            const float b1 = __ldg(bias + ng + 1);
            float v00 = acc[i][j][0] + b0;
            float v01 = acc[i][j][1] + b1;
            float v10 = acc[i][j][2] + b0;
            float v11 = acc[i][j][3] + b1;
            if (RELU) {
                v00 = fmaxf(v00, 0.0f); v01 = fmaxf(v01, 0.0f);
                v10 = fmaxf(v10, 0.0f); v11 = fmaxf(v11, 0.0f);
            }
            const size_t o0 = (size_t)mg0 * DIMC + ng;
            const size_t o1 = (size_t)(mg0 + 8) * DIMC + ng;
            if (OUT_F32) {
                *(float2*)(Cf + o0) = make_float2(v00, v01);
                *(float2*)(Cf + o1) = make_float2(v10, v11);
            } else {
                *(__half2*)(Ch + o0) = __floats2half2_rn(v00, v01);
                *(__half2*)(Ch + o1) = __floats2half2_rn(v10, v11);
            }
        }
    }
}

// ---------------------------------------------------------------------------
// Sliding-window attention (fp32)
// ---------------------------------------------------------------------------
__global__ __launch_bounds__(256)
void swa_kernel(const float* __restrict__ q, const float* __restrict__ k,
                const float* __restrict__ v, float* __restrict__ out)
{
    __shared__ float4 qs4[DIMC / 4];
    __shared__ float  sc[WIN];

    const int row = blockIdx.x;
    const int b   = row >> 11;
    const int s   = row & (SEQ - 1);
    const int tid = threadIdx.x;
    const int warp = tid >> 5;
    const int lane = tid & 31;
    const float scale = 0.03125f;

    {
        float4 t = ((const float4*)(q + (size_t)row * DIMC))[tid];
        t.x *= scale; t.y *= scale; t.z *= scale; t.w *= scale;
        qs4[tid] = t;
    }
    __syncthreads();

    for (int p = warp; p < WIN; p += 8) {
        const int j = s - HALF + p;
        if (j < 0 || j >= SEQ) {
            if (lane == 0) sc[p] = -__int_as_float(0x7f800000);
            continue;
        }
        const float4* kr = (const float4*)(k + ((size_t)b * SEQ + j) * DIMC);
        float acc = 0.0f;
        for (int c = lane; c < DIMC / 4; c += 32) {
            float4 kv = kr[c];
            float4 qv = qs4[c];
            acc = fmaf(qv.x, kv.x, acc);
            acc = fmaf(qv.y, kv.y, acc);
            acc = fmaf(qv.z, kv.z, acc);
            acc = fmaf(qv.w, kv.w, acc);
        }
        #pragma unroll
        for (int off = 16; off; off >>= 1)
            acc += __shfl_xor_sync(0xffffffffu, acc, off);
        if (lane == 0) sc[p] = acc;
    }
    __syncthreads();

    if (tid < 32) {
        float mx = -__int_as_float(0x7f800000);
        for (int p = tid; p < WIN; p += 32) mx = fmaxf(mx, sc[p]);
        #pragma unroll
        for (int off = 16; off; off >>= 1)
            mx = fmaxf(mx, __shfl_xor_sync(0xffffffffu, mx, off));
        float sum = 0.0f;
        float e[3]; int np = 0;
        for (int p = tid; p < WIN; p += 32) {
            float ev = __expf(sc[p] - mx);
            e[np++] = ev;
            sum += ev;
        }
        #pragma unroll
        for (int off = 16; off; off >>= 1)
            sum += __shfl_xor_sync(0xffffffffu, sum, off);
        float inv = 1.0f / sum;
        np = 0;
        for (int p = tid; p < WIN; p += 32) sc[p] = e[np++] * inv;
    }
    __syncthreads();

    const int j0 = (s - HALF < 0) ? 0 : s - HALF;
    const int j1 = (s + HALF > SEQ - 1) ? SEQ - 1 : s + HALF;
    float4 acc = make_float4(0.f, 0.f, 0.f, 0.f);
    const float4* vb = (const float4*)(v + (size_t)b * SEQ * DIMC);
    for (int j = j0; j <= j1; j++) {
        const float w = sc[j - (s - HALF)];
        float4 vv = vb[(size_t)j * (DIMC / 4) + tid];
        acc.x = fmaf(w, vv.x, acc.x);
        acc.y = fmaf(w, vv.y, acc.y);
        acc.z = fmaf(w, vv.z, acc.z);
        acc.w = fmaf(w, vv.w, acc.w);
    }
    ((float4*)(out + (size_t)row * DIMC))[tid] = acc;
}

// ---------------------------------------------------------------------------
// launch
// ---------------------------------------------------------------------------
extern "C" void kernel_launch(void* const* d_in, const int* in_sizes, int n_in,
                              void* d_out, int out_size)
{
    const float* x     = (const float*)d_in[0];
    const float* nm_w1 = (const float*)d_in[1];
    const float* nm_b1 = (const float*)d_in[2];
    const float* nm_w2 = (const float*)d_in[3];
    const float* nm_b2 = (const float*)d_in[4];
    const float* q_w   = (const float*)d_in[5];
    const float* q_b   = (const float*)d_in[6];
    const float* k_w   = (const float*)d_in[7];
    const float* k_b   = (const float*)d_in[8];
    const float* v_w   = (const float*)d_in[9];
    const float* v_b   = (const float*)d_in[10];
    float* out = (float*)d_out;

    __half *xh, *h, *m, *w;
    float *qkv, *bqkv;
    cudaGetSymbolAddress((void**)&xh, g_xh);
    cudaGetSymbolAddress((void**)&h, g_h);
    cudaGetSymbolAddress((void**)&m, g_m);
    cudaGetSymbolAddress((void**)&w, g_w);
    cudaGetSymbolAddress((void**)&qkv, g_qkv);
    cudaGetSymbolAddress((void**)&bqkv, g_bqkv);

    cudaFuncSetAttribute(gemm_f16_kernel<1,0,1>, cudaFuncAttributeMaxDynamicSharedMemorySize, GEMM_SMEM);
    cudaFuncSetAttribute(gemm_f16_kernel<0,0,1>, cudaFuncAttributeMaxDynamicSharedMemorySize, GEMM_SMEM);
    cudaFuncSetAttribute(gemm_f16_kernel<0,1,3>, cudaFuncAttributeMaxDynamicSharedMemorySize, GEMM_SMEM);

    constexpr size_t WSZ = (size_t)DIMC * DIMC;

    // launch 1: conversions + bias concat
    prep_kernel<<<4096 + 5 * 1024 + 1, 256>>>(x, nm_w1, nm_w2, q_w, k_w, v_w,
                                              q_b, k_b, v_b, xh, w, bqkv);

    dim3 grid(8, 32);
    gemm_f16_kernel<1,0,1><<<grid, 256, GEMM_SMEM>>>(xh, w + 0 * WSZ, nm_b1, nullptr, h);
    gemm_f16_kernel<0,0,1><<<grid, 256, GEMM_SMEM>>>(h,  w + 1 * WSZ, nm_b2, nullptr, m);

    dim3 gridQKV(24, 32);
    gemm_f16_kernel<0,1,3><<<gridQKV, 256, GEMM_SMEM>>>(m, w + 2 * WSZ, bqkv, qkv, nullptr);

    const float* q = qkv;
    const float* k = qkv + (size_t)M_TOT * DIMC;
    const float* v = qkv + 2 * (size_t)M_TOT * DIMC;
    swa_kernel<<<M_TOT, 256>>>(q, k, v, out);
}

// round 7
// speedup vs baseline: 5.0874x; 1.4090x over previous
#include <cuda_runtime.h>
#include <cuda_fp16.h>
#include <cstdint>

// ---------------------------------------------------------------------------
// LongTermMemory: fp16 HMMA GEMMs (unchanged mainloop) + NEW flash-style
// sliding-window attention (HMMA QK^T and PV, 32-query x 96-key bands).
// ---------------------------------------------------------------------------

constexpr int M_TOT = 4096;
constexpr int DIMC  = 1024;
constexpr int SEQ   = 2048;

// ---------------- scratch ----------------
__device__ __half g_xh[M_TOT * DIMC];
__device__ __half g_h[M_TOT * DIMC];
__device__ __half g_m[M_TOT * DIMC];
__device__ __half g_qkvh[3][M_TOT * DIMC];
__device__ float g_bqkv[3 * DIMC];
__device__ __half g_w[5][DIMC * DIMC];   // transposed: Wt[n][k], fp16

// ---------------------------------------------------------------------------
// helpers
// ---------------------------------------------------------------------------
__device__ __forceinline__ uint32_t smem_u32(const void* p) {
    uint32_t a;
    asm("{ .reg .u64 t; cvta.to.shared.u64 t, %1; cvt.u32.u64 %0, t; }"
        : "=r"(a) : "l"(p));
    return a;
}
__device__ __forceinline__ void cp_async16(uint32_t saddr, const void* gaddr) {
    asm volatile("cp.async.cg.shared.global [%0], [%1], 16;"
                 :: "r"(saddr), "l"(gaddr));
}
#define CP_COMMIT()  asm volatile("cp.async.commit_group;" ::: "memory")
#define CP_WAIT(N)   asm volatile("cp.async.wait_group %0;" :: "n"(N) : "memory")

__device__ __forceinline__ void ldmatrix_x4(uint32_t& r0, uint32_t& r1,
                                            uint32_t& r2, uint32_t& r3,
                                            uint32_t addr) {
    asm volatile("ldmatrix.sync.aligned.m8n8.x4.shared.b16 {%0,%1,%2,%3}, [%4];"
                 : "=r"(r0), "=r"(r1), "=r"(r2), "=r"(r3) : "r"(addr));
}
__device__ __forceinline__ void ldmatrix_x2(uint32_t& r0, uint32_t& r1,
                                            uint32_t addr) {
    asm volatile("ldmatrix.sync.aligned.m8n8.x2.shared.b16 {%0,%1}, [%2];"
                 : "=r"(r0), "=r"(r1) : "r"(addr));
}
__device__ __forceinline__ void ldmatrix_x4_trans(uint32_t& r0, uint32_t& r1,
                                                  uint32_t& r2, uint32_t& r3,
                                                  uint32_t addr) {
    asm volatile("ldmatrix.sync.aligned.m8n8.x4.trans.shared.b16 {%0,%1,%2,%3}, [%4];"
                 : "=r"(r0), "=r"(r1), "=r"(r2), "=r"(r3) : "r"(addr));
}

__device__ __forceinline__ void mma16816(float* d, const uint32_t* a,
                                         uint32_t b0, uint32_t b1) {
    asm volatile(
        "mma.sync.aligned.m16n8k16.row.col.f32.f16.f16.f32 "
        "{%0,%1,%2,%3}, {%4,%5,%6,%7}, {%8,%9}, {%0,%1,%2,%3};"
        : "+f"(d[0]), "+f"(d[1]), "+f"(d[2]), "+f"(d[3])
        : "r"(a[0]), "r"(a[1]), "r"(a[2]), "r"(a[3]), "r"(b0), "r"(b1));
}

// ---------------------------------------------------------------------------
// prep kernel: x->fp16, 5 weight transposes, qkv bias concat.
// ---------------------------------------------------------------------------
__global__ __launch_bounds__(256)
void prep_kernel(const float* __restrict__ x,
                 const float* __restrict__ w1, const float* __restrict__ w2,
                 const float* __restrict__ qw, const float* __restrict__ kw,
                 const float* __restrict__ vw,
                 const float* __restrict__ qb, const float* __restrict__ kb,
                 const float* __restrict__ vb,
                 __half* __restrict__ xh, __half* __restrict__ wt,
                 float* __restrict__ bqkv)
{
    const int b = blockIdx.x;
    const int tid = threadIdx.x;
    if (b < 4096) {
        const int row0 = (b >> 5) << 5;
        const int col0 = (b & 31) << 5;
        const int r = tid >> 3;
        const int c = (tid & 7) << 2;
        const size_t o = (size_t)(row0 + r) * DIMC + col0 + c;
        float4 v = *(const float4*)(x + o);
        __half2* hp = (__half2*)(xh + o);
        hp[0] = __floats2half2_rn(v.x, v.y);
        hp[1] = __floats2half2_rn(v.z, v.w);
    } else if (b < 4096 + 5120) {
        __shared__ float t[32][33];
        const int wb = b - 4096;
        const int wi = wb >> 10;
        const int within = wb & 1023;
        const int n0 = (within & 31) << 5;
        const int k0 = (within >> 5) << 5;
        const float* W = (wi == 0) ? w1 : (wi == 1) ? w2 :
                         (wi == 2) ? qw : (wi == 3) ? kw : vw;
        __half* out = wt + (size_t)wi * DIMC * DIMC;
        const int tx = tid & 31, ty = tid >> 5;
        #pragma unroll
        for (int i = ty; i < 32; i += 8)
            t[i][tx] = W[(size_t)(k0 + i) * DIMC + n0 + tx];
        __syncthreads();
        #pragma unroll
        for (int i = ty; i < 32; i += 8)
            out[(size_t)(n0 + i) * DIMC + k0 + tx] = __float2half_rn(t[tx][i]);
    } else {
        for (int i = tid; i < DIMC; i += 256) {
            bqkv[i]            = qb[i];
            bqkv[DIMC + i]     = kb[i];
            bqkv[2 * DIMC + i] = vb[i];
        }
    }
}

// ---------------------------------------------------------------------------
// HMMA GEMM (as R6): CTA 128x128, BK=32, 3-stage cp.async, 2 CTAs/SM.
// NSTACK>1: grid.x = 8*NSTACK, B/bias/out selected by bx>>3.
// ---------------------------------------------------------------------------
constexpr int BK = 32;
constexpr int STRIDE = 40;
constexpr int TILE_E = 128 * STRIDE;
constexpr int TILE_B = TILE_E * 2;
constexpr int STAGE_B = 2 * TILE_B;
constexpr int GEMM_SMEM = 3 * STAGE_B;

template <int RELU, int OUT_F32, int NSTACK>
__global__ __launch_bounds__(256, 2)
void gemm_f16_kernel(const __half* __restrict__ A_h,
                     const __half* __restrict__ B_base,
                     const float* __restrict__ bias_base,
                     float* __restrict__ Cf_base,
                     __half* __restrict__ Ch_base)
{
    extern __shared__ __half sm[];
    const uint32_t sb = smem_u32(sm);

    const int tid  = threadIdx.x;
    const int wid  = tid >> 5;
    const int lane = tid & 31;
    int bx = blockIdx.x;
    const int by = blockIdx.y;
    int wsel = 0;
    if (NSTACK > 1) { wsel = bx >> 3; bx &= 7; }

    const __half* B   = B_base + (size_t)wsel * DIMC * DIMC;
    const float* bias = bias_base + wsel * DIMC;
    float* Cf = OUT_F32 ? (Cf_base + (size_t)wsel * M_TOT * DIMC) : nullptr;
    __half* Ch = OUT_F32 ? nullptr : (Ch_base + (size_t)wsel * M_TOT * DIMC);

    const int wr = wid >> 2;
    const int wc = wid & 3;
    const int g   = lane >> 2;
    const int tig = lane & 3;

    const int lrow = tid >> 1;
    const int lsel = (tid & 1) * 16;

    const __half* gA = A_h + (size_t)(by * 128 + lrow) * DIMC + lsel;
    const __half* gB = B   + (size_t)(bx * 128 + lrow) * DIMC + lsel;
    const uint32_t sofs = (lrow * STRIDE + lsel) * 2;

    auto load_stage = [&](int buf, int kt) {
        const uint32_t s0 = sb + buf * STAGE_B + sofs;
        const int go = kt * BK;
        cp_async16(s0,               gA + go);
        cp_async16(s0 + 16,          gA + go + 8);
        cp_async16(s0 + TILE_B,      gB + go);
        cp_async16(s0 + TILE_B + 16, gB + go + 8);
    };

    const int lr15 = lane & 15;
    const int lk8  = (lane >> 4) << 3;
    const uint32_t aBase = ((uint32_t)(wr * 64 + lr15) * STRIDE + lk8) * 2;
    const uint32_t bBase = ((uint32_t)(wc * 32 + lr15) * STRIDE + lk8) * 2 + TILE_B;

    float acc[4][4][4];
    #pragma unroll
    for (int i = 0; i < 4; i++)
        #pragma unroll
        for (int j = 0; j < 4; j++)
            #pragma unroll
            for (int r = 0; r < 4; r++) acc[i][j][r] = 0.0f;

    load_stage(0, 0); CP_COMMIT();
    load_stage(1, 1); CP_COMMIT();

    constexpr int NKT = DIMC / BK;
    int buf = 0;
    for (int kt = 0; kt < NKT; kt++) {
        CP_WAIT(1);
        __syncthreads();
        if (kt + 2 < NKT) {
            int nb = buf + 2; if (nb >= 3) nb -= 3;
            load_stage(nb, kt + 2);
        }
        CP_COMMIT();

        const uint32_t st = sb + buf * STAGE_B;

        uint32_t ah[2][4][4], bf[2][2][4];
        #pragma unroll
        for (int s = 0; s < 2; s++) {
            const uint32_t kc = (uint32_t)(s * 16) * 2;
            #pragma unroll
            for (int i = 0; i < 4; i++) {
                const uint32_t ro = st + aBase + (uint32_t)(i * 16 * STRIDE) * 2 + kc;
                ldmatrix_x4(ah[s][i][0], ah[s][i][1], ah[s][i][2], ah[s][i][3], ro);
            }
            #pragma unroll
            for (int jj = 0; jj < 2; jj++) {
                const uint32_t ro = st + bBase + (uint32_t)(jj * 16 * STRIDE) * 2 + kc;
                ldmatrix_x4(bf[s][jj][0], bf[s][jj][1], bf[s][jj][2], bf[s][jj][3], ro);
            }
        }
        #pragma unroll
        for (int s = 0; s < 2; s++)
            #pragma unroll
            for (int i = 0; i < 4; i++)
                #pragma unroll
                for (int j = 0; j < 4; j++) {
                    const int jj = j >> 1, sel = j & 1;
                    mma16816(acc[s & 0 ? 0 : i][j], ah[s][i], bf[s][jj][sel], bf[s][jj][sel + 2]);
                }

        if (++buf == 3) buf = 0;
    }

    #pragma unroll
    for (int i = 0; i < 4; i++) {
        const int mg0 = by * 128 + wr * 64 + i * 16 + g;
        #pragma unroll
        for (int j = 0; j < 4; j++) {
            const int ng = bx * 128 + wc * 32 + j * 8 + tig * 2;
            const float b0 = __ldg(bias + ng);
            const float b1 = __ldg(bias + ng + 1);
            float v00 = acc[i][j][0] + b0;
            float v01 = acc[i][j][1] + b1;
            float v10 = acc[i][j][2] + b0;
            float v11 = acc[i][j][3] + b1;
            if (RELU) {
                v00 = fmaxf(v00, 0.0f); v01 = fmaxf(v01, 0.0f);
                v10 = fmaxf(v10, 0.0f); v11 = fmaxf(v11, 0.0f);
            }
            const size_t o0 = (size_t)mg0 * DIMC + ng;
            const size_t o1 = (size_t)(mg0 + 8) * DIMC + ng;
            if (OUT_F32) {
                *(float2*)(Cf + o0) = make_float2(v00, v01);
                *(float2*)(Cf + o1) = make_float2(v10, v11);
            } else {
                *(__half2*)(Ch + o0) = __floats2half2_rn(v00, v01);
                *(__half2*)(Ch + o1) = __floats2half2_rn(v10, v11);
            }
        }
    }
}

// ---------------------------------------------------------------------------
// Flash-style sliding-window attention.
// CTA = 32 queries (one batch), key band = 96 rows [s0-32, s0+63].
// Phase 1: S = (Q K^T)/32 via HMMA (D streamed in 64-chunks), exact mask.
// Softmax fp32 in smem. Phase 2: O = P V via HMMA (D streamed in 128-chunks,
// V via ldmatrix.trans). 128 CTAs, 256 threads.
// ---------------------------------------------------------------------------
constexpr int QB = 32;          // queries per CTA
constexpr int KBAND = 96;       // key band
constexpr int BKD = 64;         // phase-1 d-chunk
constexpr int DC = 128;         // phase-2 d-chunk

constexpr int QS_STRIDE = 72;   // elements (64 + 8)
constexpr int VS_STRIDE = 136;  // elements (128 + 8)
constexpr int SF_STRIDE = 100;  // floats
constexpr int PS_STRIDE = 104;  // halves

constexpr int Q_ST = QB * QS_STRIDE * 2;        // 4608 B
constexpr int K_ST = KBAND * QS_STRIDE * 2;     // 13824 B
constexpr int V_ST = KBAND * VS_STRIDE * 2;     // 26112 B
constexpr int OFF_Q = 0;
constexpr int OFF_K = OFF_Q + 3 * Q_ST;         // 13824
constexpr int OFF_S = OFF_K + 3 * K_ST;         // 55296
constexpr int OFF_P = OFF_S + QB * SF_STRIDE * 4;   // 68096
constexpr int OFF_V = OFF_P + QB * PS_STRIDE * 2;   // 74752
constexpr int SWA_SMEM = OFF_V + 3 * V_ST;      // 153088

__global__ __launch_bounds__(256, 1)
void swa_flash_kernel(const __half* __restrict__ q,
                      const __half* __restrict__ k,
                      const __half* __restrict__ v,
                      float* __restrict__ out)
{
    extern __shared__ char smc[];
    const uint32_t sb = smem_u32(smc);

    const int tid  = threadIdx.x;
    const int wid  = tid >> 5;
    const int lane = tid & 31;
    const int bid  = blockIdx.x;           // 0..127
    const int batch = bid >> 6;
    const int s0 = (bid & 63) * QB;

    const int wr = wid >> 2;                // 0..1 (16 query rows)
    const int wc = wid & 3;                 // 0..3 (24 score cols / 32 out cols)
    const int lr15 = lane & 15;
    const int lk8  = (lane >> 4) << 3;

    const size_t qbase = (size_t)(batch * SEQ + s0) * DIMC;
    const size_t kvbase = (size_t)batch * SEQ * DIMC;

    // ---------------- phase 1: scores ----------------
    // loaders
    const int qrow = tid >> 3;              // 0..31
    const int qch  = (tid & 7) * 8;         // element offset within 64-chunk
    auto load_qk = [&](int buf, int kt) {
        const int d0 = kt * BKD + qch;
        // Q: 32 rows, 1 chunk per thread
        cp_async16(sb + OFF_Q + buf * Q_ST + (qrow * QS_STRIDE + qch) * 2,
                   q + qbase + (size_t)qrow * DIMC + d0);
        // K: 96 rows, 3 chunks per thread
        #pragma unroll
        for (int i = 0; i < 3; i++) {
            const int krow = qrow + 32 * i;
            int jg = s0 - 32 + krow;
            jg = jg < 0 ? 0 : (jg >= SEQ ? SEQ - 1 : jg);
            cp_async16(sb + OFF_K + buf * K_ST + (krow * QS_STRIDE + qch) * 2,
                       k + kvbase + (size_t)jg * DIMC + d0);
        }
    };

    float accS[3][4];
    #pragma unroll
    for (int j = 0; j < 3; j++)
        #pragma unroll
        for (int r = 0; r < 4; r++) accS[j][r] = 0.0f;

    load_qk(0, 0); CP_COMMIT();
    load_qk(1, 1); CP_COMMIT();

    constexpr int NKT1 = DIMC / BKD;   // 16
    int buf = 0;
    for (int kt = 0; kt < NKT1; kt++) {
        CP_WAIT(1);
        __syncthreads();
        if (kt + 2 < NKT1) {
            int nb = buf + 2; if (nb >= 3) nb -= 3;
            load_qk(nb, kt + 2);
        }
        CP_COMMIT();

        const uint32_t sq = sb + OFF_Q + buf * Q_ST;
        const uint32_t sk = sb + OFF_K + buf * K_ST;

        #pragma unroll
        for (int ks = 0; ks < 4; ks++) {
            uint32_t a[4];
            ldmatrix_x4(a[0], a[1], a[2], a[3],
                        sq + ((uint32_t)(wr * 16 + lr15) * QS_STRIDE + ks * 16 + lk8) * 2);
            uint32_t br[3][2];
            #pragma unroll
            for (int gN = 0; gN < 3; gN++) {
                ldmatrix_x2(br[gN][0], br[gN][1],
                            sk + ((uint32_t)(wc * 24 + gN * 8 + (lane & 7)) * QS_STRIDE
                                  + ks * 16 + ((lane >> 3) & 1) * 8) * 2);
            }
            #pragma unroll
            for (int gN = 0; gN < 3; gN++)
                mma16816(accS[gN], a, br[gN][0], br[gN][1]);
        }
        if (++buf == 3) buf = 0;
    }

    // write masked + scaled scores
    {
        float* Sf = (float*)(smc + OFF_S);
        const int r0 = wr * 16 + (lane >> 2);
        const int c0 = wc * 24 + (lane & 3) * 2;
        #pragma unroll
        for (int gN = 0; gN < 3; gN++) {
            #pragma unroll
            for (int half = 0; half < 2; half++) {
                const int qi = r0 + half * 8;
                #pragma unroll
                for (int cc = 0; cc < 2; cc++) {
                    const int kj = c0 + gN * 8 + cc;
                    const int jg = s0 - 32 + kj;
                    const int d  = kj - qi;
                    const bool valid = (jg >= 0) && (jg < SEQ) && (d >= 0) && (d <= 64);
                    Sf[qi * SF_STRIDE + kj] =
                        valid ? accS[gN][half * 2 + cc] * 0.03125f : -1e30f;
                }
            }
        }
    }
    __syncthreads();

    // softmax: 8 threads per row
    {
        float* Sf = (float*)(smc + OFF_S);
        __half* Ps = (__half*)(smc + OFF_P);
        const int srow = tid >> 3;
        const int ssub = tid & 7;
        float vals[12];
        float mx = -1e30f;
        #pragma unroll
        for (int i = 0; i < 12; i++) {
            vals[i] = Sf[srow * SF_STRIDE + ssub * 12 + i];
            mx = fmaxf(mx, vals[i]);
        }
        #pragma unroll
        for (int off = 4; off; off >>= 1)
            mx = fmaxf(mx, __shfl_xor_sync(0xffffffffu, mx, off));
        float sum = 0.0f;
        #pragma unroll
        for (int i = 0; i < 12; i++) {
            vals[i] = __expf(vals[i] - mx);
            sum += vals[i];
        }
        #pragma unroll
        for (int off = 4; off; off >>= 1)
            sum += __shfl_xor_sync(0xffffffffu, sum, off);
        const float inv = 1.0f / sum;
        #pragma unroll
        for (int i = 0; i < 12; i++)
            Ps[srow * PS_STRIDE + ssub * 12 + i] = __float2half(vals[i] * inv);
    }
    CP_WAIT(0);
    __syncthreads();

    // ---------------- phase 2: O = P V ----------------
    const int vrow16 = tid >> 4;            // 0..15
    const int vch    = (tid & 15) * 8;      // element offset in 128-chunk
    auto load_v = [&](int vbuf, int c) {
        const int d0 = c * DC + vch;
        #pragma unroll
        for (int i = 0; i < 6; i++) {
            const int krow = vrow16 + 16 * i;
            int jg = s0 - 32 + krow;
            jg = jg < 0 ? 0 : (jg >= SEQ ? SEQ - 1 : jg);
            cp_async16(sb + OFF_V + vbuf * V_ST + (krow * VS_STRIDE + vch) * 2,
                       v + kvbase + (size_t)jg * DIMC + d0);
        }
    };

    load_v(0, 0); CP_COMMIT();
    load_v(1, 1); CP_COMMIT();

    const uint32_t psb = sb + OFF_P;
    int vb = 0;
    constexpr int NC = DIMC / DC;   // 8
    for (int c = 0; c < NC; c++) {
        CP_WAIT(1);
        __syncthreads();
        if (c + 2 < NC) {
            int nb = vb + 2; if (nb >= 3) nb -= 3;
            load_v(nb, c + 2);
        }
        CP_COMMIT();

        const uint32_t sv = sb + OFF_V + vb * V_ST;

        float acc2[4][4];
        #pragma unroll
        for (int j = 0; j < 4; j++)
            #pragma unroll
            for (int r = 0; r < 4; r++) acc2[j][r] = 0.0f;

        #pragma unroll
        for (int ks = 0; ks < 6; ks++) {
            uint32_t p[4];
            ldmatrix_x4(p[0], p[1], p[2], p[3],
                        psb + ((uint32_t)(wr * 16 + lr15) * PS_STRIDE + ks * 16 + lk8) * 2);
            uint32_t vbf[2][4];
            #pragma unroll
            for (int h = 0; h < 2; h++) {
                ldmatrix_x4_trans(vbf[h][0], vbf[h][1], vbf[h][2], vbf[h][3],
                                  sv + ((uint32_t)(ks * 16 + lr15) * VS_STRIDE
                                        + wc * 32 + h * 16 + lk8) * 2);
            }
            #pragma unroll
            for (int j = 0; j < 4; j++)
                mma16816(acc2[j], p, vbf[j >> 1][(j & 1) * 2], vbf[j >> 1][(j & 1) * 2 + 1]);
        }

        // write out chunk
        const int r0 = wr * 16 + (lane >> 2);
        #pragma unroll
        for (int j = 0; j < 4; j++) {
            const int col = c * DC + wc * 32 + j * 8 + (lane & 3) * 2;
            const size_t o0 = qbase + (size_t)r0 * DIMC + col;
            const size_t o1 = qbase + (size_t)(r0 + 8) * DIMC + col;
            *(float2*)(out + o0) = make_float2(acc2[j][0], acc2[j][1]);
            *(float2*)(out + o1) = make_float2(acc2[j][2], acc2[j][3]);
        }
        if (++vb == 3) vb = 0;
    }
}

// ---------------------------------------------------------------------------
// launch
// ---------------------------------------------------------------------------
extern "C" void kernel_launch(void* const* d_in, const int* in_sizes, int n_in,
                              void* d_out, int out_size)
{
    const float* x     = (const float*)d_in[0];
    const float* nm_w1 = (const float*)d_in[1];
    const float* nm_b1 = (const float*)d_in[2];
    const float* nm_w2 = (const float*)d_in[3];
    const float* nm_b2 = (const float*)d_in[4];
    const float* q_w   = (const float*)d_in[5];
    const float* q_b   = (const float*)d_in[6];
    const float* k_w   = (const float*)d_in[7];
    const float* k_b   = (const float*)d_in[8];
    const float* v_w   = (const float*)d_in[9];
    const float* v_b   = (const float*)d_in[10];
    float* out = (float*)d_out;

    __half *xh, *h, *m, *w, *qkvh;
    float *bqkv;
    cudaGetSymbolAddress((void**)&xh, g_xh);
    cudaGetSymbolAddress((void**)&h, g_h);
    cudaGetSymbolAddress((void**)&m, g_m);
    cudaGetSymbolAddress((void**)&w, g_w);
    cudaGetSymbolAddress((void**)&qkvh, g_qkvh);
    cudaGetSymbolAddress((void**)&bqkv, g_bqkv);

    cudaFuncSetAttribute(gemm_f16_kernel<1,0,1>, cudaFuncAttributeMaxDynamicSharedMemorySize, GEMM_SMEM);
    cudaFuncSetAttribute(gemm_f16_kernel<0,0,1>, cudaFuncAttributeMaxDynamicSharedMemorySize, GEMM_SMEM);
    cudaFuncSetAttribute(gemm_f16_kernel<0,0,3>, cudaFuncAttributeMaxDynamicSharedMemorySize, GEMM_SMEM);
    cudaFuncSetAttribute(swa_flash_kernel, cudaFuncAttributeMaxDynamicSharedMemorySize, SWA_SMEM);

    constexpr size_t WSZ = (size_t)DIMC * DIMC;

    prep_kernel<<<4096 + 5 * 1024 + 1, 256>>>(x, nm_w1, nm_w2, q_w, k_w, v_w,
                                              q_b, k_b, v_b, xh, w, bqkv);

    dim3 grid(8, 32);
    gemm_f16_kernel<1,0,1><<<grid, 256, GEMM_SMEM>>>(xh, w + 0 * WSZ, nm_b1, nullptr, h);
    gemm_f16_kernel<0,0,1><<<grid, 256, GEMM_SMEM>>>(h,  w + 1 * WSZ, nm_b2, nullptr, m);

    dim3 gridQKV(24, 32);
    gemm_f16_kernel<0,0,3><<<gridQKV, 256, GEMM_SMEM>>>(m, w + 2 * WSZ, bqkv, nullptr, qkvh);

    const __half* qh = qkvh;
    const __half* kh = qkvh + (size_t)M_TOT * DIMC;
    const __half* vh = qkvh + 2 * (size_t)M_TOT * DIMC;
    swa_flash_kernel<<<128, 256, SWA_SMEM>>>(qh, kh, vh, out);
}